// round 2
// baseline (speedup 1.0000x reference)
#include <cuda_runtime.h>
#include <math.h>

#define NN 50000
#define EE 800000
#define DD 128
#define HH 128
#define KU (DD + HH)
#define BN_EPS 1e-3f

// ---------------- scratch (device globals; no allocation allowed) ----------
__device__ float g_T[NN * HH];      // FFN intermediate
__device__ float g_P[NN * HH];      // prep output per node
__device__ float g_AGG[NN * HH];    // aggregated neighbour messages
__device__ float g_Wp0[DD * HH];
__device__ float g_Wp1[HH * HH];
__device__ float g_Wu0[KU * HH];
__device__ float g_Wu1[HH * HH];
__device__ float g_bp0[HH], g_bp1[HH], g_bu0[HH], g_bu1[HH];
__device__ int   g_cnt[NN];
__device__ int   g_off[NN + 1];
__device__ int   g_cur[NN];
__device__ int   g_nbr[EE];
__device__ float g_wgt[EE];

// ---------------- BN fold: W'[k][j] = s[k]*W[k][j], b'[j] = b[j]+sum_k t[k]W[k][j]
__global__ void fold_kernel(const float* __restrict__ g, const float* __restrict__ b,
                            const float* __restrict__ m, const float* __restrict__ v,
                            const float* __restrict__ W, const float* __restrict__ bias,
                            int K, float* __restrict__ Wout, float* __restrict__ bout) {
    int j = blockIdx.x;        // output column 0..127
    int k = threadIdx.x;       // input row 0..K-1 (blockDim == K)
    __shared__ float red[256];
    float s = g[k] * rsqrtf(v[k] + BN_EPS);
    float t = b[k] - m[k] * s;
    float w = W[k * HH + j];
    Wout[k * HH + j] = s * w;
    red[k] = t * w;
    __syncthreads();
    for (int st = blockDim.x >> 1; st > 0; st >>= 1) {
        if (k < st) red[k] += red[k + st];
        __syncthreads();
    }
    if (k == 0) bout[j] = bias[j] + red[0];
}

// ---------------- CSR build --------------------------------------------------
__global__ void zero_kernel() {
    int i = blockIdx.x * blockDim.x + threadIdx.x;
    if (i < NN) { g_cnt[i] = 0; g_cur[i] = 0; }
}

__global__ void count_kernel(const int* __restrict__ edges) {
    int e = blockIdx.x * blockDim.x + threadIdx.x;
    if (e < EE) atomicAdd(&g_cnt[edges[e]], 1);
}

// single-block exclusive scan of g_cnt -> g_off
__global__ void scan_kernel() {
    const int T = 1024;
    int t = threadIdx.x;
    const int per = (NN + T - 1) / T;
    int start = t * per;
    int end   = start + per; if (end > NN) end = NN;
    int s = 0;
    for (int i = start; i < end; i++) s += g_cnt[i];
    __shared__ int sh[T];
    sh[t] = s;
    __syncthreads();
    for (int ofs = 1; ofs < T; ofs <<= 1) {
        int v = (t >= ofs) ? sh[t - ofs] : 0;
        __syncthreads();
        sh[t] += v;
        __syncthreads();
    }
    int run = sh[t] - s;   // exclusive prefix for this thread's range
    for (int i = start; i < end; i++) { g_off[i] = run; run += g_cnt[i]; }
    if (t == T - 1) g_off[NN] = sh[T - 1];
}

__global__ void fill_kernel(const int* __restrict__ edges, const float* __restrict__ ew) {
    int e = blockIdx.x * blockDim.x + threadIdx.x;
    if (e < EE) {
        int dst = edges[e];
        int nbr = edges[EE + e];
        int pos = g_off[dst] + atomicAdd(&g_cur[dst], 1);
        g_nbr[pos] = nbr;
        g_wgt[pos] = ew[e];
    }
}

// ---------------- aggregation: one warp per node, gather rows of g_P ---------
__global__ void aggregate_kernel() {
    int warp = (blockIdx.x * blockDim.x + threadIdx.x) >> 5;
    int lane = threadIdx.x & 31;
    if (warp >= NN) return;
    int s = g_off[warp], e = g_off[warp + 1];
    float4 acc = make_float4(0.f, 0.f, 0.f, 0.f);
    for (int i = s; i < e; i++) {
        int nb  = __ldg(&g_nbr[i]);
        float w = __ldg(&g_wgt[i]);
        float4 p = __ldg((const float4*)&g_P[nb * HH + lane * 4]);
        acc.x += w * p.x; acc.y += w * p.y; acc.z += w * p.z; acc.w += w * p.w;
    }
    float inv = (e > s) ? 1.0f / (float)(e - s) : 0.0f;
    acc.x *= inv; acc.y *= inv; acc.z *= inv; acc.w *= inv;
    *(float4*)&g_AGG[warp * HH + lane * 4] = acc;
}

// ---------------- fused GEMM + bias + exact gelu -----------------------------
// C[M x 128] = gelu( A0[M x K0] @ W[0:K0] + A1[M x K1] @ W[K0:K0+K1] + bias )
// W is (K0+K1) x 128 row-major (already BN-folded). A matrices row-major, ld = K.
__device__ __forceinline__ float gelu_exact(float x) {
    return 0.5f * x * (1.0f + erff(x * 0.70710678118654752f));
}

__global__ __launch_bounds__(256, 2) void gemm_gelu_kernel(
    const float* __restrict__ A0, int K0,
    const float* __restrict__ A1, int K1,
    const float* __restrict__ W, const float* __restrict__ bias,
    float* __restrict__ C, int M)
{
    __shared__ float As[8][128];   // As[k][m]
    __shared__ float Bs[8][128];   // Bs[k][n]

    const int tid = threadIdx.x;
    const int tx = tid & 15;       // 0..15 -> 8 output cols each
    const int ty = tid >> 4;       // 0..15 -> 8 output rows each
    const int bm = blockIdx.x * 128;

    // A-load mapping: row r = tid & 127, k-quad q = tid >> 7 (0/1 -> k 0..3 / 4..7)
    const int lr = tid & 127;
    const int lq = tid >> 7;
    // B-load mapping: row kk = tid >> 5, col j = (tid & 31) * 4
    const int bk = tid >> 5;
    const int bj = (tid & 31) * 4;

    float acc[8][8];
#pragma unroll
    for (int i = 0; i < 8; i++)
#pragma unroll
        for (int j = 0; j < 8; j++) acc[i][j] = 0.0f;

    const int Ktot = K0 + K1;
    const int grow = bm + lr;
    const bool rok = (grow < M);

    for (int kc = 0; kc < Ktot; kc += 8) {
        const float* A; int lda, kloc;
        if (kc < K0) { A = A0; lda = K0; kloc = kc; }
        else         { A = A1; lda = K1; kloc = kc - K0; }

        float4 av = make_float4(0.f, 0.f, 0.f, 0.f);
        if (rok) av = *(const float4*)&A[grow * lda + kloc + lq * 4];
        float4 bv = *(const float4*)&W[(kc + bk) * 128 + bj];

        __syncthreads();
        As[lq * 4 + 0][lr] = av.x;
        As[lq * 4 + 1][lr] = av.y;
        As[lq * 4 + 2][lr] = av.z;
        As[lq * 4 + 3][lr] = av.w;
        *(float4*)&Bs[bk][bj] = bv;
        __syncthreads();

#pragma unroll
        for (int kk = 0; kk < 8; kk++) {
            float a[8], bfr[8];
            *(float4*)&a[0]   = *(const float4*)&As[kk][ty * 8];
            *(float4*)&a[4]   = *(const float4*)&As[kk][ty * 8 + 4];
            *(float4*)&bfr[0] = *(const float4*)&Bs[kk][tx * 8];
            *(float4*)&bfr[4] = *(const float4*)&Bs[kk][tx * 8 + 4];
#pragma unroll
            for (int i = 0; i < 8; i++)
#pragma unroll
                for (int j = 0; j < 8; j++) acc[i][j] += a[i] * bfr[j];
        }
    }

    float bs[8];
    *(float4*)&bs[0] = *(const float4*)&bias[tx * 8];
    *(float4*)&bs[4] = *(const float4*)&bias[tx * 8 + 4];

#pragma unroll
    for (int i = 0; i < 8; i++) {
        int r = bm + ty * 8 + i;
        if (r < M) {
            float out[8];
#pragma unroll
            for (int j = 0; j < 8; j++) out[j] = gelu_exact(acc[i][j] + bs[j]);
            *(float4*)&C[r * 128 + tx * 8]     = *(float4*)&out[0];
            *(float4*)&C[r * 128 + tx * 8 + 4] = *(float4*)&out[4];
        }
    }
}

// ---------------- launch -----------------------------------------------------
extern "C" void kernel_launch(void* const* d_in, const int* in_sizes, int n_in,
                              void* d_out, int out_size) {
    const float* node_repr = (const float*)d_in[0];
    const int*   edges     = (const int*)d_in[1];
    const float* ew        = (const float*)d_in[2];
    // prep layer 0: idx 3..8, prep layer 1: 9..14, upd layer 0: 15..20, upd layer 1: 21..26
    const float *p0g = (const float*)d_in[3],  *p0b = (const float*)d_in[4],
                *p0m = (const float*)d_in[5],  *p0v = (const float*)d_in[6],
                *p0W = (const float*)d_in[7],  *p0bi = (const float*)d_in[8];
    const float *p1g = (const float*)d_in[9],  *p1b = (const float*)d_in[10],
                *p1m = (const float*)d_in[11], *p1v = (const float*)d_in[12],
                *p1W = (const float*)d_in[13], *p1bi = (const float*)d_in[14];
    const float *u0g = (const float*)d_in[15], *u0b = (const float*)d_in[16],
                *u0m = (const float*)d_in[17], *u0v = (const float*)d_in[18],
                *u0W = (const float*)d_in[19], *u0bi = (const float*)d_in[20];
    const float *u1g = (const float*)d_in[21], *u1b = (const float*)d_in[22],
                *u1m = (const float*)d_in[23], *u1v = (const float*)d_in[24],
                *u1W = (const float*)d_in[25], *u1bi = (const float*)d_in[26];
    float* out = (float*)d_out;

    float *Wp0, *Wp1, *Wu0, *Wu1, *bp0, *bp1, *bu0, *bu1, *T, *P, *AGG;
    cudaGetSymbolAddress((void**)&Wp0, g_Wp0);
    cudaGetSymbolAddress((void**)&Wp1, g_Wp1);
    cudaGetSymbolAddress((void**)&Wu0, g_Wu0);
    cudaGetSymbolAddress((void**)&Wu1, g_Wu1);
    cudaGetSymbolAddress((void**)&bp0, g_bp0);
    cudaGetSymbolAddress((void**)&bp1, g_bp1);
    cudaGetSymbolAddress((void**)&bu0, g_bu0);
    cudaGetSymbolAddress((void**)&bu1, g_bu1);
    cudaGetSymbolAddress((void**)&T,   g_T);
    cudaGetSymbolAddress((void**)&P,   g_P);
    cudaGetSymbolAddress((void**)&AGG, g_AGG);

    // 1) fold BN into weights
    fold_kernel<<<128, 128>>>(p0g, p0b, p0m, p0v, p0W, p0bi, DD, Wp0, bp0);
    fold_kernel<<<128, 128>>>(p1g, p1b, p1m, p1v, p1W, p1bi, HH, Wp1, bp1);
    fold_kernel<<<128, 256>>>(u0g, u0b, u0m, u0v, u0W, u0bi, KU, Wu0, bu0);
    fold_kernel<<<128, 128>>>(u1g, u1b, u1m, u1v, u1W, u1bi, HH, Wu1, bu1);

    // 2) CSR build
    zero_kernel<<<(NN + 255) / 256, 256>>>();
    count_kernel<<<(EE + 255) / 256, 256>>>(edges);
    scan_kernel<<<1, 1024>>>();
    fill_kernel<<<(EE + 255) / 256, 256>>>(edges, ew);

    // 3) prep FFN on unique nodes (NOT per edge: messages = prep_ffn(node)[nbr])
    const int gm = (NN + 127) / 128;
    gemm_gelu_kernel<<<gm, 256>>>(node_repr, DD, nullptr, 0, Wp0, bp0, T, NN);
    gemm_gelu_kernel<<<gm, 256>>>(T,         HH, nullptr, 0, Wp1, bp1, P, NN);

    // 4) segment mean via CSR gather (warp per node)
    aggregate_kernel<<<(NN * 32 + 255) / 256, 256>>>();

    // 5) update FFN: concat handled as split-K GEMM
    gemm_gelu_kernel<<<gm, 256>>>(node_repr, DD, AGG, HH, Wu0, bu0, T, NN);
    gemm_gelu_kernel<<<gm, 256>>>(T,         HH, nullptr, 0, Wu1, bu1, out, NN);
}

// round 6
// speedup vs baseline: 1.7904x; 1.7904x over previous
#include <cuda_runtime.h>
#include <math.h>
#include <stdint.h>

#define NN 50000
#define EE 800000
#define DD 128
#define HH 128
#define KU (DD + HH)
#define BN_EPS 1e-3f

// ---------------- scratch (device globals; no allocation allowed) ----------
__device__ float g_T[NN * HH];      // FFN intermediate
__device__ float g_P[NN * HH];      // prep output per node
__device__ float g_AGG[NN * HH];    // aggregated neighbour messages
__device__ float g_Wp0[DD * HH];
__device__ float g_Wp1[HH * HH];
__device__ float g_Wu0[KU * HH];
__device__ float g_Wu1[HH * HH];
__device__ float g_bp0[HH], g_bp1[HH], g_bu0[HH], g_bu1[HH];
__device__ int   g_cnt[NN];
__device__ int   g_off[NN + 1];
__device__ int   g_cur[NN];
__device__ int   g_nbr[EE];
__device__ float g_wgt[EE];

// tf32 conversion: destination MUST be a .b32 register in PTX
__device__ __forceinline__ uint32_t to_tf32_bits(float x) {
    uint32_t r;
    asm("cvt.rna.tf32.f32 %0, %1;" : "=r"(r) : "f"(x));
    return r;
}

// ---------------- BN fold (merged, 4 matrices in one launch) ----------------
// W'[k][j] = tf32(s[k]*W[k][j]), b'[j] = b[j] + sum_k t[k]*W[k][j]
struct FoldArgs {
    const float *g, *b, *m, *v, *W, *bi;
    float *Wo, *bo;
    int K;
};

__global__ void fold4_kernel(FoldArgs a0, FoldArgs a1, FoldArgs a2, FoldArgs a3) {
    FoldArgs a;
    switch (blockIdx.y) {
        case 0: a = a0; break;
        case 1: a = a1; break;
        case 2: a = a2; break;
        default: a = a3; break;
    }
    int j = blockIdx.x;        // output column 0..127
    int k = threadIdx.x;       // input row (blockDim = 256)
    __shared__ float red[256];
    float contrib = 0.0f;
    if (k < a.K) {
        float s = a.g[k] * rsqrtf(a.v[k] + BN_EPS);
        float t = a.b[k] - a.m[k] * s;
        float w = a.W[k * HH + j];
        a.Wo[k * HH + j] = __uint_as_float(to_tf32_bits(s * w));
        contrib = t * w;
    }
    red[k] = contrib;
    __syncthreads();
    for (int st = 128; st > 0; st >>= 1) {
        if (k < st) red[k] += red[k + st];
        __syncthreads();
    }
    if (k == 0) a.bo[j] = a.bi[j] + red[0];
}

// ---------------- CSR build --------------------------------------------------
__global__ void zero_kernel() {
    int i = blockIdx.x * blockDim.x + threadIdx.x;
    if (i < NN) { g_cnt[i] = 0; g_cur[i] = 0; }
}

__global__ void count_kernel(const int* __restrict__ edges) {
    int e = blockIdx.x * blockDim.x + threadIdx.x;
    if (e < EE) atomicAdd(&g_cnt[edges[e]], 1);
}

// single-block exclusive scan of g_cnt -> g_off
__global__ void scan_kernel() {
    const int T = 1024;
    int t = threadIdx.x;
    const int per = (NN + T - 1) / T;
    int start = t * per;
    int end   = start + per; if (end > NN) end = NN;
    int s = 0;
    for (int i = start; i < end; i++) s += g_cnt[i];
    __shared__ int sh[T];
    sh[t] = s;
    __syncthreads();
    for (int ofs = 1; ofs < T; ofs <<= 1) {
        int v = (t >= ofs) ? sh[t - ofs] : 0;
        __syncthreads();
        sh[t] += v;
        __syncthreads();
    }
    int run = sh[t] - s;   // exclusive prefix for this thread's range
    for (int i = start; i < end; i++) { g_off[i] = run; run += g_cnt[i]; }
    if (t == T - 1) g_off[NN] = sh[T - 1];
}

__global__ void fill_kernel(const int* __restrict__ edges, const float* __restrict__ ew) {
    int e = blockIdx.x * blockDim.x + threadIdx.x;
    if (e < EE) {
        int dst = edges[e];
        int nbr = edges[EE + e];
        int pos = g_off[dst] + atomicAdd(&g_cur[dst], 1);
        g_nbr[pos] = nbr;
        g_wgt[pos] = ew[e];
    }
}

// ---------------- aggregation: one warp per node, gather rows of g_P ---------
__global__ void aggregate_kernel() {
    int warp = (blockIdx.x * blockDim.x + threadIdx.x) >> 5;
    int lane = threadIdx.x & 31;
    if (warp >= NN) return;
    int s = g_off[warp], e = g_off[warp + 1];
    float4 acc = make_float4(0.f, 0.f, 0.f, 0.f);
    for (int i = s; i < e; i++) {
        int nb  = __ldg(&g_nbr[i]);
        float w = __ldg(&g_wgt[i]);
        float4 p = __ldg((const float4*)&g_P[nb * HH + lane * 4]);
        acc.x += w * p.x; acc.y += w * p.y; acc.z += w * p.z; acc.w += w * p.w;
    }
    float inv = (e > s) ? 1.0f / (float)(e - s) : 0.0f;
    acc.x *= inv; acc.y *= inv; acc.z *= inv; acc.w *= inv;
    *(float4*)&g_AGG[warp * HH + lane * 4] = acc;
}

// ---------------- tf32 tensor-core GEMM + bias + exact gelu -----------------
// C[M x 128] = gelu( A0[M x K0] @ W[0:K0] + A1[M x K1] @ W[K0:K0+K1] + bias )
// W is (K0+K1) x 128 row-major, already BN-folded and tf32-rounded.
__device__ __forceinline__ float gelu_exact(float x) {
    return 0.5f * x * (1.0f + erff(x * 0.70710678118654752f));
}

__device__ __forceinline__ void mma_tf32(float* d, const uint32_t* a, const uint32_t* b) {
    asm volatile(
        "mma.sync.aligned.m16n8k8.row.col.f32.tf32.tf32.f32 "
        "{%0,%1,%2,%3}, {%4,%5,%6,%7}, {%8,%9}, {%0,%1,%2,%3};\n"
        : "+f"(d[0]), "+f"(d[1]), "+f"(d[2]), "+f"(d[3])
        : "r"(a[0]), "r"(a[1]), "r"(a[2]), "r"(a[3]), "r"(b[0]), "r"(b[1]));
}

#define BM 128
#define BN 128
#define BK 16
#define AS_STRIDE 20     // 16 + 4 pad: conflict-free fragment reads
#define BS_STRIDE 136    // 128 + 8 pad: conflict-free fragment reads

__global__ __launch_bounds__(256, 2) void gemm_tf32_gelu(
    const float* __restrict__ A0, int K0,
    const float* __restrict__ A1, int K1,
    const float* __restrict__ W, const float* __restrict__ bias,
    float* __restrict__ C, int M)
{
    __shared__ float As[BM][AS_STRIDE];   // [m][k]
    __shared__ float Bs[BK][BS_STRIDE];   // [k][n]

    const int tid  = threadIdx.x;
    const int lane = tid & 31;
    const int wid  = tid >> 5;
    const int wm = (wid & 3) * 32;    // warp row base in tile (4 warps down)
    const int wn = (wid >> 2) * 64;   // warp col base in tile (2 warps across)
    const int bm = blockIdx.x * BM;

    // A loader: row = tid>>1 (128 rows), col half = (tid&1)*8 -> 2 float4
    const int alr = tid >> 1;
    const int alc = (tid & 1) * 8;
    const int grow = bm + alr;
    const bool rok = (grow < M);
    // B loader: row k = tid>>4 (16 rows), col = (tid&15)*8 -> 2 float4
    const int blk = tid >> 4;
    const int blc = (tid & 15) * 8;

    const int gi = lane >> 2;   // groupID
    const int ti = lane & 3;    // threadID_in_group

    float acc[2][8][4];
#pragma unroll
    for (int i = 0; i < 2; i++)
#pragma unroll
        for (int j = 0; j < 8; j++)
#pragma unroll
            for (int c = 0; c < 4; c++) acc[i][j][c] = 0.0f;

    const int Ktot = K0 + K1;

    for (int kc = 0; kc < Ktot; kc += BK) {
        const float* A; int lda, kloc;
        if (kc < K0) { A = A0; lda = K0; kloc = kc; }
        else         { A = A1; lda = K1; kloc = kc - K0; }

        float4 av0 = make_float4(0.f, 0.f, 0.f, 0.f);
        float4 av1 = av0;
        if (rok) {
            const float* ap = &A[grow * lda + kloc + alc];
            av0 = *(const float4*)(ap);
            av1 = *(const float4*)(ap + 4);
        }
        float4 bv0 = *(const float4*)&W[(kc + blk) * 128 + blc];
        float4 bv1 = *(const float4*)&W[(kc + blk) * 128 + blc + 4];

        __syncthreads();
        As[alr][alc + 0] = __uint_as_float(to_tf32_bits(av0.x));
        As[alr][alc + 1] = __uint_as_float(to_tf32_bits(av0.y));
        As[alr][alc + 2] = __uint_as_float(to_tf32_bits(av0.z));
        As[alr][alc + 3] = __uint_as_float(to_tf32_bits(av0.w));
        As[alr][alc + 4] = __uint_as_float(to_tf32_bits(av1.x));
        As[alr][alc + 5] = __uint_as_float(to_tf32_bits(av1.y));
        As[alr][alc + 6] = __uint_as_float(to_tf32_bits(av1.z));
        As[alr][alc + 7] = __uint_as_float(to_tf32_bits(av1.w));
        // W already tf32-rounded by fold
        *(float4*)&Bs[blk][blc]     = bv0;
        *(float4*)&Bs[blk][blc + 4] = bv1;
        __syncthreads();

#pragma unroll
        for (int ks = 0; ks < 2; ks++) {
            const int k0 = ks * 8;
            uint32_t af[2][4];
#pragma unroll
            for (int i = 0; i < 2; i++) {
                const int r = wm + 16 * i + gi;
                af[i][0] = __float_as_uint(As[r][k0 + ti]);
                af[i][1] = __float_as_uint(As[r + 8][k0 + ti]);
                af[i][2] = __float_as_uint(As[r][k0 + ti + 4]);
                af[i][3] = __float_as_uint(As[r + 8][k0 + ti + 4]);
            }
            uint32_t bf[8][2];
#pragma unroll
            for (int j = 0; j < 8; j++) {
                const int col = wn + 8 * j + gi;
                bf[j][0] = __float_as_uint(Bs[k0 + ti][col]);
                bf[j][1] = __float_as_uint(Bs[k0 + ti + 4][col]);
            }
#pragma unroll
            for (int i = 0; i < 2; i++)
#pragma unroll
                for (int j = 0; j < 8; j++)
                    mma_tf32(acc[i][j], af[i], bf[j]);
        }
    }

    // Epilogue: bias + gelu, float2 stores
#pragma unroll
    for (int j = 0; j < 8; j++) {
        const int col = wn + 8 * j + ti * 2;
        const float b0 = bias[col];
        const float b1 = bias[col + 1];
#pragma unroll
        for (int i = 0; i < 2; i++) {
            const int r0 = bm + wm + 16 * i + gi;
            const int r1 = r0 + 8;
            if (r0 < M) {
                float2 o;
                o.x = gelu_exact(acc[i][j][0] + b0);
                o.y = gelu_exact(acc[i][j][1] + b1);
                *(float2*)&C[r0 * 128 + col] = o;
            }
            if (r1 < M) {
                float2 o;
                o.x = gelu_exact(acc[i][j][2] + b0);
                o.y = gelu_exact(acc[i][j][3] + b1);
                *(float2*)&C[r1 * 128 + col] = o;
            }
        }
    }
}

// ---------------- launch -----------------------------------------------------
extern "C" void kernel_launch(void* const* d_in, const int* in_sizes, int n_in,
                              void* d_out, int out_size) {
    const float* node_repr = (const float*)d_in[0];
    const int*   edges     = (const int*)d_in[1];
    const float* ew        = (const float*)d_in[2];
    const float *p0g = (const float*)d_in[3],  *p0b = (const float*)d_in[4],
                *p0m = (const float*)d_in[5],  *p0v = (const float*)d_in[6],
                *p0W = (const float*)d_in[7],  *p0bi = (const float*)d_in[8];
    const float *p1g = (const float*)d_in[9],  *p1b = (const float*)d_in[10],
                *p1m = (const float*)d_in[11], *p1v = (const float*)d_in[12],
                *p1W = (const float*)d_in[13], *p1bi = (const float*)d_in[14];
    const float *u0g = (const float*)d_in[15], *u0b = (const float*)d_in[16],
                *u0m = (const float*)d_in[17], *u0v = (const float*)d_in[18],
                *u0W = (const float*)d_in[19], *u0bi = (const float*)d_in[20];
    const float *u1g = (const float*)d_in[21], *u1b = (const float*)d_in[22],
                *u1m = (const float*)d_in[23], *u1v = (const float*)d_in[24],
                *u1W = (const float*)d_in[25], *u1bi = (const float*)d_in[26];
    float* out = (float*)d_out;

    float *Wp0, *Wp1, *Wu0, *Wu1, *bp0, *bp1, *bu0, *bu1, *T, *P, *AGG;
    cudaGetSymbolAddress((void**)&Wp0, g_Wp0);
    cudaGetSymbolAddress((void**)&Wp1, g_Wp1);
    cudaGetSymbolAddress((void**)&Wu0, g_Wu0);
    cudaGetSymbolAddress((void**)&Wu1, g_Wu1);
    cudaGetSymbolAddress((void**)&bp0, g_bp0);
    cudaGetSymbolAddress((void**)&bp1, g_bp1);
    cudaGetSymbolAddress((void**)&bu0, g_bu0);
    cudaGetSymbolAddress((void**)&bu1, g_bu1);
    cudaGetSymbolAddress((void**)&T,   g_T);
    cudaGetSymbolAddress((void**)&P,   g_P);
    cudaGetSymbolAddress((void**)&AGG, g_AGG);

    // 1) fold BN into weights (tf32-rounded), all four matrices in one launch
    FoldArgs fa0 = {p0g, p0b, p0m, p0v, p0W, p0bi, Wp0, bp0, DD};
    FoldArgs fa1 = {p1g, p1b, p1m, p1v, p1W, p1bi, Wp1, bp1, HH};
    FoldArgs fa2 = {u0g, u0b, u0m, u0v, u0W, u0bi, Wu0, bu0, KU};
    FoldArgs fa3 = {u1g, u1b, u1m, u1v, u1W, u1bi, Wu1, bu1, HH};
    fold4_kernel<<<dim3(128, 4), 256>>>(fa0, fa1, fa2, fa3);

    // 2) CSR build
    zero_kernel<<<(NN + 255) / 256, 256>>>();
    count_kernel<<<(EE + 255) / 256, 256>>>(edges);
    scan_kernel<<<1, 1024>>>();
    fill_kernel<<<(EE + 255) / 256, 256>>>(edges, ew);

    // 3) prep FFN on unique nodes (messages = prep_ffn(node)[nbr])
    const int gm = (NN + BM - 1) / BM;
    gemm_tf32_gelu<<<gm, 256>>>(node_repr, DD, nullptr, 0, Wp0, bp0, T, NN);
    gemm_tf32_gelu<<<gm, 256>>>(T,         HH, nullptr, 0, Wp1, bp1, P, NN);

    // 4) segment mean via CSR gather (warp per node)
    aggregate_kernel<<<(NN * 32 + 255) / 256, 256>>>();

    // 5) update FFN: concat handled as split-K GEMM
    gemm_tf32_gelu<<<gm, 256>>>(node_repr, DD, AGG, HH, Wu0, bu0, T, NN);
    gemm_tf32_gelu<<<gm, 256>>>(T,         HH, nullptr, 0, Wu1, bu1, out, NN);
}

// round 7
// speedup vs baseline: 2.2574x; 1.2608x over previous
#include <cuda_runtime.h>
#include <math.h>
#include <stdint.h>

#define NN 50000
#define EE 800000
#define DD 128
#define HH 128
#define KU (DD + HH)
#define BN_EPS 1e-3f

#define SCAN_B 256
#define SCAN_NB ((NN + SCAN_B - 1) / SCAN_B)   // 196

// ---------------- scratch (device globals; no allocation allowed) ----------
__device__ float g_T[NN * HH];      // FFN intermediate
__device__ float g_P[NN * HH];      // prep output per node
__device__ float g_AGG[NN * HH];    // aggregated neighbour messages
__device__ float g_Wp0[DD * HH];
__device__ float g_Wp1[HH * HH];
__device__ float g_Wu0[KU * HH];
__device__ float g_Wu1[HH * HH];
__device__ float g_bp0[HH], g_bp1[HH], g_bu0[HH], g_bu1[HH];
__device__ int   g_cnt[NN];
__device__ int   g_off[NN + 1];
__device__ int   g_cur[NN];
__device__ int   g_nbr[EE];
__device__ float g_wgt[EE];
__device__ int   g_blksum[SCAN_NB];
__device__ int   g_blkoff[SCAN_NB];

// tf32 conversion: destination MUST be a .b32 register in PTX
__device__ __forceinline__ uint32_t to_tf32_bits(float x) {
    uint32_t r;
    asm("cvt.rna.tf32.f32 %0, %1;" : "=r"(r) : "f"(x));
    return r;
}

// ---------------- BN fold (4 matrices) + cnt zeroing, one launch ------------
struct FoldArgs {
    const float *g, *b, *m, *v, *W, *bi;
    float *Wo, *bo;
    int K;
};

__global__ void fold4zero_kernel(FoldArgs a0, FoldArgs a1, FoldArgs a2, FoldArgs a3) {
    if (blockIdx.y == 4) {
        // zero lane: grid.x = SCAN_NB blocks of 256
        int i = blockIdx.x * blockDim.x + threadIdx.x;
        if (i < NN) { g_cnt[i] = 0; g_cur[i] = 0; }
        return;
    }
    if (blockIdx.x >= 128) return;
    FoldArgs a;
    switch (blockIdx.y) {
        case 0: a = a0; break;
        case 1: a = a1; break;
        case 2: a = a2; break;
        default: a = a3; break;
    }
    int j = blockIdx.x;        // output column 0..127
    int k = threadIdx.x;       // input row (blockDim = 256)
    __shared__ float red[256];
    float contrib = 0.0f;
    if (k < a.K) {
        float s = a.g[k] * rsqrtf(a.v[k] + BN_EPS);
        float t = a.b[k] - a.m[k] * s;
        float w = a.W[k * HH + j];
        a.Wo[k * HH + j] = __uint_as_float(to_tf32_bits(s * w));
        contrib = t * w;
    }
    red[k] = contrib;
    __syncthreads();
    for (int st = 128; st > 0; st >>= 1) {
        if (k < st) red[k] += red[k + st];
        __syncthreads();
    }
    if (k == 0) a.bo[j] = a.bi[j] + red[0];
}

// ---------------- CSR build --------------------------------------------------
__global__ void count_kernel(const int* __restrict__ edges) {
    int e = blockIdx.x * blockDim.x + threadIdx.x;
    if (e < EE) atomicAdd(&g_cnt[edges[e]], 1);
}

// Phase A: per-block sums of g_cnt
__global__ void scanA_kernel() {
    __shared__ int sh[SCAN_B];
    int t = threadIdx.x;
    int i = blockIdx.x * SCAN_B + t;
    sh[t] = (i < NN) ? g_cnt[i] : 0;
    __syncthreads();
    for (int st = SCAN_B / 2; st > 0; st >>= 1) {
        if (t < st) sh[t] += sh[t + st];
        __syncthreads();
    }
    if (t == 0) g_blksum[blockIdx.x] = sh[0];
}

// Phase B: 1 block, exclusive scan of the block sums
__global__ void scanB_kernel() {
    __shared__ int sh[SCAN_B];
    int t = threadIdx.x;
    int v = (t < SCAN_NB) ? g_blksum[t] : 0;
    sh[t] = v;
    __syncthreads();
    for (int ofs = 1; ofs < SCAN_B; ofs <<= 1) {
        int u = (t >= ofs) ? sh[t - ofs] : 0;
        __syncthreads();
        sh[t] += u;
        __syncthreads();
    }
    if (t < SCAN_NB) g_blkoff[t] = sh[t] - v;   // exclusive
    if (t == SCAN_B - 1) g_off[NN] = sh[t];     // total (== EE)
}

// Phase C: local exclusive scan + block offset -> g_off
__global__ void scanC_kernel() {
    __shared__ int sh[SCAN_B];
    int t = threadIdx.x;
    int i = blockIdx.x * SCAN_B + t;
    int v = (i < NN) ? g_cnt[i] : 0;
    sh[t] = v;
    __syncthreads();
    for (int ofs = 1; ofs < SCAN_B; ofs <<= 1) {
        int u = (t >= ofs) ? sh[t - ofs] : 0;
        __syncthreads();
        sh[t] += u;
        __syncthreads();
    }
    if (i < NN) g_off[i] = g_blkoff[blockIdx.x] + sh[t] - v;
}

__global__ void fill_kernel(const int* __restrict__ edges, const float* __restrict__ ew) {
    int e = blockIdx.x * blockDim.x + threadIdx.x;
    if (e < EE) {
        int dst = edges[e];
        int nbr = edges[EE + e];
        int pos = g_off[dst] + atomicAdd(&g_cur[dst], 1);
        g_nbr[pos] = nbr;
        g_wgt[pos] = ew[e];
    }
}

// ---------------- aggregation: one warp per node, gather rows of g_P ---------
__global__ void aggregate_kernel() {
    int warp = (blockIdx.x * blockDim.x + threadIdx.x) >> 5;
    int lane = threadIdx.x & 31;
    if (warp >= NN) return;
    int s = g_off[warp], e = g_off[warp + 1];
    float4 acc = make_float4(0.f, 0.f, 0.f, 0.f);
    int i = s;
    for (; i + 2 <= e; i += 2) {
        int nb0  = __ldg(&g_nbr[i]);
        int nb1  = __ldg(&g_nbr[i + 1]);
        float w0 = __ldg(&g_wgt[i]);
        float w1 = __ldg(&g_wgt[i + 1]);
        float4 p0 = __ldg((const float4*)&g_P[nb0 * HH + lane * 4]);
        float4 p1 = __ldg((const float4*)&g_P[nb1 * HH + lane * 4]);
        acc.x += w0 * p0.x + w1 * p1.x;
        acc.y += w0 * p0.y + w1 * p1.y;
        acc.z += w0 * p0.z + w1 * p1.z;
        acc.w += w0 * p0.w + w1 * p1.w;
    }
    if (i < e) {
        int nb  = __ldg(&g_nbr[i]);
        float w = __ldg(&g_wgt[i]);
        float4 p = __ldg((const float4*)&g_P[nb * HH + lane * 4]);
        acc.x += w * p.x; acc.y += w * p.y; acc.z += w * p.z; acc.w += w * p.w;
    }
    float inv = (e > s) ? 1.0f / (float)(e - s) : 0.0f;
    acc.x *= inv; acc.y *= inv; acc.z *= inv; acc.w *= inv;
    *(float4*)&g_AGG[warp * HH + lane * 4] = acc;
}

// ---------------- tf32 tensor-core GEMM + bias + exact gelu -----------------
__device__ __forceinline__ float gelu_exact(float x) {
    return 0.5f * x * (1.0f + erff(x * 0.70710678118654752f));
}

__device__ __forceinline__ void mma_tf32(float* d, const uint32_t* a, const uint32_t* b) {
    asm volatile(
        "mma.sync.aligned.m16n8k8.row.col.f32.tf32.tf32.f32 "
        "{%0,%1,%2,%3}, {%4,%5,%6,%7}, {%8,%9}, {%0,%1,%2,%3};\n"
        : "+f"(d[0]), "+f"(d[1]), "+f"(d[2]), "+f"(d[3])
        : "r"(a[0]), "r"(a[1]), "r"(a[2]), "r"(a[3]), "r"(b[0]), "r"(b[1]));
}

#define BM 128
#define BN 128
#define BK 16
#define AS_STRIDE 20     // 16 + 4 pad: conflict-free fragment reads
#define BS_STRIDE 136    // 128 + 8 pad: conflict-free fragment reads

__device__ __forceinline__ void load_tile(
    const float* __restrict__ A0, int K0,
    const float* __restrict__ A1, int K1,
    const float* __restrict__ W,
    int kc, bool rok, int grow, int alc, int blk, int blc,
    float4& av0, float4& av1, float4& bv0, float4& bv1)
{
    const float* A; int lda, kloc;
    if (kc < K0) { A = A0; lda = K0; kloc = kc; }
    else         { A = A1; lda = K1; kloc = kc - K0; }
    av0 = make_float4(0.f, 0.f, 0.f, 0.f);
    av1 = av0;
    if (rok) {
        const float* ap = &A[grow * lda + kloc + alc];
        av0 = *(const float4*)(ap);
        av1 = *(const float4*)(ap + 4);
    }
    bv0 = *(const float4*)&W[(kc + blk) * 128 + blc];
    bv1 = *(const float4*)&W[(kc + blk) * 128 + blc + 4];
}

__global__ __launch_bounds__(256, 2) void gemm_tf32_gelu(
    const float* __restrict__ A0, int K0,
    const float* __restrict__ A1, int K1,
    const float* __restrict__ W, const float* __restrict__ bias,
    float* __restrict__ C, int M)
{
    __shared__ float As[BM][AS_STRIDE];   // [m][k]
    __shared__ float Bs[BK][BS_STRIDE];   // [k][n]

    const int tid  = threadIdx.x;
    const int lane = tid & 31;
    const int wid  = tid >> 5;
    const int wm = (wid & 3) * 32;    // warp row base (4 warps down)
    const int wn = (wid >> 2) * 64;   // warp col base (2 warps across)
    const int bm = blockIdx.x * BM;

    const int alr = tid >> 1;
    const int alc = (tid & 1) * 8;
    const int grow = bm + alr;
    const bool rok = (grow < M);
    const int blk = tid >> 4;
    const int blc = (tid & 15) * 8;

    const int gi = lane >> 2;   // groupID
    const int ti = lane & 3;    // threadID_in_group

    float acc[2][8][4];
#pragma unroll
    for (int i = 0; i < 2; i++)
#pragma unroll
        for (int j = 0; j < 8; j++)
#pragma unroll
            for (int c = 0; c < 4; c++) acc[i][j][c] = 0.0f;

    const int Ktot = K0 + K1;

    // software pipeline: prefetch tile kc+BK while doing mma on tile kc
    float4 av0, av1, bv0, bv1;
    load_tile(A0, K0, A1, K1, W, 0, rok, grow, alc, blk, blc, av0, av1, bv0, bv1);

    for (int kc = 0; kc < Ktot; kc += BK) {
        __syncthreads();   // previous mma done reading smem
        As[alr][alc + 0] = __uint_as_float(to_tf32_bits(av0.x));
        As[alr][alc + 1] = __uint_as_float(to_tf32_bits(av0.y));
        As[alr][alc + 2] = __uint_as_float(to_tf32_bits(av0.z));
        As[alr][alc + 3] = __uint_as_float(to_tf32_bits(av0.w));
        As[alr][alc + 4] = __uint_as_float(to_tf32_bits(av1.x));
        As[alr][alc + 5] = __uint_as_float(to_tf32_bits(av1.y));
        As[alr][alc + 6] = __uint_as_float(to_tf32_bits(av1.z));
        As[alr][alc + 7] = __uint_as_float(to_tf32_bits(av1.w));
        *(float4*)&Bs[blk][blc]     = bv0;
        *(float4*)&Bs[blk][blc + 4] = bv1;
        __syncthreads();

        if (kc + BK < Ktot)
            load_tile(A0, K0, A1, K1, W, kc + BK, rok, grow, alc, blk, blc, av0, av1, bv0, bv1);

#pragma unroll
        for (int ks = 0; ks < 2; ks++) {
            const int k0 = ks * 8;
            uint32_t af[2][4];
#pragma unroll
            for (int i = 0; i < 2; i++) {
                const int r = wm + 16 * i + gi;
                af[i][0] = __float_as_uint(As[r][k0 + ti]);
                af[i][1] = __float_as_uint(As[r + 8][k0 + ti]);
                af[i][2] = __float_as_uint(As[r][k0 + ti + 4]);
                af[i][3] = __float_as_uint(As[r + 8][k0 + ti + 4]);
            }
            uint32_t bf[8][2];
#pragma unroll
            for (int j = 0; j < 8; j++) {
                const int col = wn + 8 * j + gi;
                bf[j][0] = __float_as_uint(Bs[k0 + ti][col]);
                bf[j][1] = __float_as_uint(Bs[k0 + ti + 4][col]);
            }
#pragma unroll
            for (int i = 0; i < 2; i++)
#pragma unroll
                for (int j = 0; j < 8; j++)
                    mma_tf32(acc[i][j], af[i], bf[j]);
        }
    }

    // Epilogue: bias + gelu, float2 stores
#pragma unroll
    for (int j = 0; j < 8; j++) {
        const int col = wn + 8 * j + ti * 2;
        const float b0 = bias[col];
        const float b1 = bias[col + 1];
#pragma unroll
        for (int i = 0; i < 2; i++) {
            const int r0 = bm + wm + 16 * i + gi;
            const int r1 = r0 + 8;
            if (r0 < M) {
                float2 o;
                o.x = gelu_exact(acc[i][j][0] + b0);
                o.y = gelu_exact(acc[i][j][1] + b1);
                *(float2*)&C[r0 * 128 + col] = o;
            }
            if (r1 < M) {
                float2 o;
                o.x = gelu_exact(acc[i][j][2] + b0);
                o.y = gelu_exact(acc[i][j][3] + b1);
                *(float2*)&C[r1 * 128 + col] = o;
            }
        }
    }
}

// ---------------- launch -----------------------------------------------------
extern "C" void kernel_launch(void* const* d_in, const int* in_sizes, int n_in,
                              void* d_out, int out_size) {
    const float* node_repr = (const float*)d_in[0];
    const int*   edges     = (const int*)d_in[1];
    const float* ew        = (const float*)d_in[2];
    const float *p0g = (const float*)d_in[3],  *p0b = (const float*)d_in[4],
                *p0m = (const float*)d_in[5],  *p0v = (const float*)d_in[6],
                *p0W = (const float*)d_in[7],  *p0bi = (const float*)d_in[8];
    const float *p1g = (const float*)d_in[9],  *p1b = (const float*)d_in[10],
                *p1m = (const float*)d_in[11], *p1v = (const float*)d_in[12],
                *p1W = (const float*)d_in[13], *p1bi = (const float*)d_in[14];
    const float *u0g = (const float*)d_in[15], *u0b = (const float*)d_in[16],
                *u0m = (const float*)d_in[17], *u0v = (const float*)d_in[18],
                *u0W = (const float*)d_in[19], *u0bi = (const float*)d_in[20];
    const float *u1g = (const float*)d_in[21], *u1b = (const float*)d_in[22],
                *u1m = (const float*)d_in[23], *u1v = (const float*)d_in[24],
                *u1W = (const float*)d_in[25], *u1bi = (const float*)d_in[26];
    float* out = (float*)d_out;

    float *Wp0, *Wp1, *Wu0, *Wu1, *bp0, *bp1, *bu0, *bu1, *T, *P, *AGG;
    cudaGetSymbolAddress((void**)&Wp0, g_Wp0);
    cudaGetSymbolAddress((void**)&Wp1, g_Wp1);
    cudaGetSymbolAddress((void**)&Wu0, g_Wu0);
    cudaGetSymbolAddress((void**)&Wu1, g_Wu1);
    cudaGetSymbolAddress((void**)&bp0, g_bp0);
    cudaGetSymbolAddress((void**)&bp1, g_bp1);
    cudaGetSymbolAddress((void**)&bu0, g_bu0);
    cudaGetSymbolAddress((void**)&bu1, g_bu1);
    cudaGetSymbolAddress((void**)&T,   g_T);
    cudaGetSymbolAddress((void**)&P,   g_P);
    cudaGetSymbolAddress((void**)&AGG, g_AGG);

    // 1) fold BN into weights (tf32-rounded) + zero cnt/cur, one launch
    FoldArgs fa0 = {p0g, p0b, p0m, p0v, p0W, p0bi, Wp0, bp0, DD};
    FoldArgs fa1 = {p1g, p1b, p1m, p1v, p1W, p1bi, Wp1, bp1, HH};
    FoldArgs fa2 = {u0g, u0b, u0m, u0v, u0W, u0bi, Wu0, bu0, KU};
    FoldArgs fa3 = {u1g, u1b, u1m, u1v, u1W, u1bi, Wu1, bu1, HH};
    fold4zero_kernel<<<dim3(SCAN_NB, 5), 256>>>(fa0, fa1, fa2, fa3);

    // 2) CSR build (multi-block scan)
    count_kernel<<<(EE + 255) / 256, 256>>>(edges);
    scanA_kernel<<<SCAN_NB, SCAN_B>>>();
    scanB_kernel<<<1, SCAN_B>>>();
    scanC_kernel<<<SCAN_NB, SCAN_B>>>();
    fill_kernel<<<(EE + 255) / 256, 256>>>(edges, ew);

    // 3) prep FFN on unique nodes (messages = prep_ffn(node)[nbr])
    const int gm = (NN + BM - 1) / BM;
    gemm_tf32_gelu<<<gm, 256>>>(node_repr, DD, nullptr, 0, Wp0, bp0, T, NN);
    gemm_tf32_gelu<<<gm, 256>>>(T,         HH, nullptr, 0, Wp1, bp1, P, NN);

    // 4) segment mean via CSR gather (warp per node)
    aggregate_kernel<<<(NN * 32 + 255) / 256, 256>>>();

    // 5) update FFN: concat handled as split-K GEMM
    gemm_tf32_gelu<<<gm, 256>>>(node_repr, DD, AGG, HH, Wu0, bu0, T, NN);
    gemm_tf32_gelu<<<gm, 256>>>(T,         HH, nullptr, 0, Wu1, bu1, out, NN);
}

// round 9
// speedup vs baseline: 2.3061x; 1.0216x over previous
#include <cuda_runtime.h>
#include <math.h>
#include <stdint.h>

#define NN 50000
#define EE 800000
#define DD 128
#define HH 128
#define KU (DD + HH)
#define BN_EPS 1e-3f

#define SCAN_B 256
#define SCAN_NB ((NN + SCAN_B - 1) / SCAN_B)   // 196

// ---------------- scratch (device globals; no allocation allowed) ----------
__device__ float g_T[NN * HH];      // FFN intermediate
__device__ float g_P[NN * HH];      // prep output per node
__device__ float g_AGG[NN * HH];    // aggregated neighbour messages
__device__ float g_PART[NN * HH];   // upd0 partial (node_repr @ Wu0_top)
__device__ float g_Wp0[DD * HH];
__device__ float g_Wp1[HH * HH];
__device__ float g_Wu0[KU * HH];
__device__ float g_Wu1[HH * HH];
__device__ float g_bp0[HH], g_bp1[HH], g_bu0[HH], g_bu1[HH];
__device__ int   g_cnt[NN];
__device__ int   g_off[NN + 1];
__device__ int   g_cur[NN];
__device__ int   g_nbr[EE];
__device__ float g_wgt[EE];
__device__ int   g_blksum[SCAN_NB];
__device__ int   g_blkoff[SCAN_NB];

// ---------------- streams/events ---------------------------------------------
// NOTE: constructed lazily on the FIRST kernel_launch call (the correctness
// run, which is NOT graph-captured) via function-local static — never at
// static-init/load time, never inside capture.
struct StreamPack {
    cudaStream_t s1, s2;
    cudaEvent_t ev_root, ev_fold, ev_csr, ev_u0a;
    StreamPack() {
        cudaStreamCreateWithFlags(&s1, cudaStreamNonBlocking);
        cudaStreamCreateWithFlags(&s2, cudaStreamNonBlocking);
        cudaEventCreateWithFlags(&ev_root, cudaEventDisableTiming);
        cudaEventCreateWithFlags(&ev_fold, cudaEventDisableTiming);
        cudaEventCreateWithFlags(&ev_csr,  cudaEventDisableTiming);
        cudaEventCreateWithFlags(&ev_u0a,  cudaEventDisableTiming);
    }
};

// tf32 conversion: destination MUST be a .b32 register in PTX
__device__ __forceinline__ uint32_t to_tf32_bits(float x) {
    uint32_t r;
    asm("cvt.rna.tf32.f32 %0, %1;" : "=r"(r) : "f"(x));
    return r;
}

// ---------------- BN fold (4 matrices, one launch) --------------------------
struct FoldArgs {
    const float *g, *b, *m, *v, *W, *bi;
    float *Wo, *bo;
    int K;
};

__global__ void fold4_kernel(FoldArgs a0, FoldArgs a1, FoldArgs a2, FoldArgs a3) {
    FoldArgs a;
    switch (blockIdx.y) {
        case 0: a = a0; break;
        case 1: a = a1; break;
        case 2: a = a2; break;
        default: a = a3; break;
    }
    int j = blockIdx.x;        // output column 0..127
    int k = threadIdx.x;       // input row (blockDim = 256)
    __shared__ float red[256];
    float contrib = 0.0f;
    if (k < a.K) {
        float s = a.g[k] * rsqrtf(a.v[k] + BN_EPS);
        float t = a.b[k] - a.m[k] * s;
        float w = a.W[k * HH + j];
        a.Wo[k * HH + j] = __uint_as_float(to_tf32_bits(s * w));
        contrib = t * w;
    }
    red[k] = contrib;
    __syncthreads();
    for (int st = 128; st > 0; st >>= 1) {
        if (k < st) red[k] += red[k + st];
        __syncthreads();
    }
    if (k == 0) a.bo[j] = a.bi[j] + red[0];
}

// ---------------- CSR build --------------------------------------------------
__global__ void count_kernel(const int* __restrict__ edges) {
    int e = blockIdx.x * blockDim.x + threadIdx.x;
    if (e < EE) atomicAdd(&g_cnt[edges[e]], 1);
}

__global__ void scanA_kernel() {
    __shared__ int sh[SCAN_B];
    int t = threadIdx.x;
    int i = blockIdx.x * SCAN_B + t;
    sh[t] = (i < NN) ? g_cnt[i] : 0;
    __syncthreads();
    for (int st = SCAN_B / 2; st > 0; st >>= 1) {
        if (t < st) sh[t] += sh[t + st];
        __syncthreads();
    }
    if (t == 0) g_blksum[blockIdx.x] = sh[0];
}

__global__ void scanB_kernel() {
    __shared__ int sh[SCAN_B];
    int t = threadIdx.x;
    int v = (t < SCAN_NB) ? g_blksum[t] : 0;
    sh[t] = v;
    __syncthreads();
    for (int ofs = 1; ofs < SCAN_B; ofs <<= 1) {
        int u = (t >= ofs) ? sh[t - ofs] : 0;
        __syncthreads();
        sh[t] += u;
        __syncthreads();
    }
    if (t < SCAN_NB) g_blkoff[t] = sh[t] - v;   // exclusive
    if (t == SCAN_B - 1) g_off[NN] = sh[t];     // total (== EE)
}

__global__ void scanC_kernel() {
    __shared__ int sh[SCAN_B];
    int t = threadIdx.x;
    int i = blockIdx.x * SCAN_B + t;
    int v = (i < NN) ? g_cnt[i] : 0;
    sh[t] = v;
    __syncthreads();
    for (int ofs = 1; ofs < SCAN_B; ofs <<= 1) {
        int u = (t >= ofs) ? sh[t - ofs] : 0;
        __syncthreads();
        sh[t] += u;
        __syncthreads();
    }
    if (i < NN) g_off[i] = g_blkoff[blockIdx.x] + sh[t] - v;
}

__global__ void fill_kernel(const int* __restrict__ edges, const float* __restrict__ ew) {
    int e = blockIdx.x * blockDim.x + threadIdx.x;
    if (e < EE) {
        int dst = edges[e];
        int nbr = edges[EE + e];
        int pos = g_off[dst] + atomicAdd(&g_cur[dst], 1);
        g_nbr[pos] = nbr;
        g_wgt[pos] = ew[e];
    }
}

// ---------------- aggregation: one warp per node, gather rows of g_P ---------
__global__ void aggregate_kernel() {
    int warp = (blockIdx.x * blockDim.x + threadIdx.x) >> 5;
    int lane = threadIdx.x & 31;
    if (warp >= NN) return;
    int s = g_off[warp], e = g_off[warp + 1];
    float4 acc = make_float4(0.f, 0.f, 0.f, 0.f);
    int i = s;
    for (; i + 4 <= e; i += 4) {
        int   nb0 = __ldg(&g_nbr[i]),     nb1 = __ldg(&g_nbr[i + 1]);
        int   nb2 = __ldg(&g_nbr[i + 2]), nb3 = __ldg(&g_nbr[i + 3]);
        float w0 = __ldg(&g_wgt[i]),      w1 = __ldg(&g_wgt[i + 1]);
        float w2 = __ldg(&g_wgt[i + 2]),  w3 = __ldg(&g_wgt[i + 3]);
        float4 p0 = __ldg((const float4*)&g_P[nb0 * HH + lane * 4]);
        float4 p1 = __ldg((const float4*)&g_P[nb1 * HH + lane * 4]);
        float4 p2 = __ldg((const float4*)&g_P[nb2 * HH + lane * 4]);
        float4 p3 = __ldg((const float4*)&g_P[nb3 * HH + lane * 4]);
        acc.x += w0 * p0.x + w1 * p1.x + w2 * p2.x + w3 * p3.x;
        acc.y += w0 * p0.y + w1 * p1.y + w2 * p2.y + w3 * p3.y;
        acc.z += w0 * p0.z + w1 * p1.z + w2 * p2.z + w3 * p3.z;
        acc.w += w0 * p0.w + w1 * p1.w + w2 * p2.w + w3 * p3.w;
    }
    for (; i < e; i++) {
        int nb  = __ldg(&g_nbr[i]);
        float w = __ldg(&g_wgt[i]);
        float4 p = __ldg((const float4*)&g_P[nb * HH + lane * 4]);
        acc.x += w * p.x; acc.y += w * p.y; acc.z += w * p.z; acc.w += w * p.w;
    }
    float inv = (e > s) ? 1.0f / (float)(e - s) : 0.0f;
    acc.x *= inv; acc.y *= inv; acc.z *= inv; acc.w *= inv;
    *(float4*)&g_AGG[warp * HH + lane * 4] = acc;
}

// ---------------- tf32 tensor-core GEMM, K=128 fixed ------------------------
// MODE 0: C = gelu(acc + bias)
// MODE 1: C = acc                       (raw partial)
// MODE 2: C = gelu(acc + bias + Cadd)
__device__ __forceinline__ float gelu_exact(float x) {
    return 0.5f * x * (1.0f + erff(x * 0.70710678118654752f));
}

__device__ __forceinline__ void mma_tf32(float* d, const uint32_t* a, const uint32_t* b) {
    asm volatile(
        "mma.sync.aligned.m16n8k8.row.col.f32.tf32.tf32.f32 "
        "{%0,%1,%2,%3}, {%4,%5,%6,%7}, {%8,%9}, {%0,%1,%2,%3};\n"
        : "+f"(d[0]), "+f"(d[1]), "+f"(d[2]), "+f"(d[3])
        : "r"(a[0]), "r"(a[1]), "r"(a[2]), "r"(a[3]), "r"(b[0]), "r"(b[1]));
}

#define BM 128
#define BK 16
#define KK 128
#define AS_STRIDE 20     // 16 + 4 pad
#define BS_STRIDE 136    // 128 + 8 pad

template <int MODE>
__global__ __launch_bounds__(256, 2) void gemm_tf32_k128(
    const float* __restrict__ A,
    const float* __restrict__ W, const float* __restrict__ bias,
    const float* __restrict__ Cadd,
    float* __restrict__ C, int M)
{
    __shared__ float As[BM][AS_STRIDE];   // [m][k]
    __shared__ float Bs[BK][BS_STRIDE];   // [k][n]

    const int tid  = threadIdx.x;
    const int lane = tid & 31;
    const int wid  = tid >> 5;
    const int wm = (wid & 3) * 32;
    const int wn = (wid >> 2) * 64;
    const int bm = blockIdx.x * BM;

    const int alr = tid >> 1;
    const int alc = (tid & 1) * 8;
    const int grow = bm + alr;
    const bool rok = (grow < M);
    const int blk = tid >> 4;
    const int blc = (tid & 15) * 8;

    const int gi = lane >> 2;
    const int ti = lane & 3;

    float acc[2][8][4];
#pragma unroll
    for (int i = 0; i < 2; i++)
#pragma unroll
        for (int j = 0; j < 8; j++)
#pragma unroll
            for (int c = 0; c < 4; c++) acc[i][j][c] = 0.0f;

    float4 av0 = make_float4(0.f,0.f,0.f,0.f), av1 = av0, bv0, bv1;
    if (rok) {
        const float* ap = &A[grow * KK + alc];
        av0 = *(const float4*)(ap);
        av1 = *(const float4*)(ap + 4);
    }
    bv0 = *(const float4*)&W[blk * 128 + blc];
    bv1 = *(const float4*)&W[blk * 128 + blc + 4];

#pragma unroll
    for (int kc = 0; kc < KK; kc += BK) {
        __syncthreads();
        As[alr][alc + 0] = __uint_as_float(to_tf32_bits(av0.x));
        As[alr][alc + 1] = __uint_as_float(to_tf32_bits(av0.y));
        As[alr][alc + 2] = __uint_as_float(to_tf32_bits(av0.z));
        As[alr][alc + 3] = __uint_as_float(to_tf32_bits(av0.w));
        As[alr][alc + 4] = __uint_as_float(to_tf32_bits(av1.x));
        As[alr][alc + 5] = __uint_as_float(to_tf32_bits(av1.y));
        As[alr][alc + 6] = __uint_as_float(to_tf32_bits(av1.z));
        As[alr][alc + 7] = __uint_as_float(to_tf32_bits(av1.w));
        *(float4*)&Bs[blk][blc]     = bv0;
        *(float4*)&Bs[blk][blc + 4] = bv1;
        __syncthreads();

        if (kc + BK < KK) {
            if (rok) {
                const float* ap = &A[grow * KK + kc + BK + alc];
                av0 = *(const float4*)(ap);
                av1 = *(const float4*)(ap + 4);
            }
            bv0 = *(const float4*)&W[(kc + BK + blk) * 128 + blc];
            bv1 = *(const float4*)&W[(kc + BK + blk) * 128 + blc + 4];
        }

#pragma unroll
        for (int ks = 0; ks < 2; ks++) {
            const int k0 = ks * 8;
            uint32_t af[2][4];
#pragma unroll
            for (int i = 0; i < 2; i++) {
                const int r = wm + 16 * i + gi;
                af[i][0] = __float_as_uint(As[r][k0 + ti]);
                af[i][1] = __float_as_uint(As[r + 8][k0 + ti]);
                af[i][2] = __float_as_uint(As[r][k0 + ti + 4]);
                af[i][3] = __float_as_uint(As[r + 8][k0 + ti + 4]);
            }
            uint32_t bf[8][2];
#pragma unroll
            for (int j = 0; j < 8; j++) {
                const int col = wn + 8 * j + gi;
                bf[j][0] = __float_as_uint(Bs[k0 + ti][col]);
                bf[j][1] = __float_as_uint(Bs[k0 + ti + 4][col]);
            }
#pragma unroll
            for (int i = 0; i < 2; i++)
#pragma unroll
                for (int j = 0; j < 8; j++)
                    mma_tf32(acc[i][j], af[i], bf[j]);
        }
    }

#pragma unroll
    for (int j = 0; j < 8; j++) {
        const int col = wn + 8 * j + ti * 2;
        float b0 = 0.f, b1 = 0.f;
        if (MODE != 1) { b0 = bias[col]; b1 = bias[col + 1]; }
#pragma unroll
        for (int i = 0; i < 2; i++) {
            const int r0 = bm + wm + 16 * i + gi;
            const int r1 = r0 + 8;
            if (r0 < M) {
                float2 o;
                if (MODE == 1)      { o.x = acc[i][j][0]; o.y = acc[i][j][1]; }
                else if (MODE == 2) {
                    o.x = gelu_exact(acc[i][j][0] + b0 + Cadd[r0 * 128 + col]);
                    o.y = gelu_exact(acc[i][j][1] + b1 + Cadd[r0 * 128 + col + 1]);
                } else {
                    o.x = gelu_exact(acc[i][j][0] + b0);
                    o.y = gelu_exact(acc[i][j][1] + b1);
                }
                *(float2*)&C[r0 * 128 + col] = o;
            }
            if (r1 < M) {
                float2 o;
                if (MODE == 1)      { o.x = acc[i][j][2]; o.y = acc[i][j][3]; }
                else if (MODE == 2) {
                    o.x = gelu_exact(acc[i][j][2] + b0 + Cadd[r1 * 128 + col]);
                    o.y = gelu_exact(acc[i][j][3] + b1 + Cadd[r1 * 128 + col + 1]);
                } else {
                    o.x = gelu_exact(acc[i][j][2] + b0);
                    o.y = gelu_exact(acc[i][j][3] + b1);
                }
                *(float2*)&C[r1 * 128 + col] = o;
            }
        }
    }
}

// ---------------- launch -----------------------------------------------------
extern "C" void kernel_launch(void* const* d_in, const int* in_sizes, int n_in,
                              void* d_out, int out_size) {
    // lazy, first-call (non-captured) stream/event creation
    static StreamPack sp;

    const float* node_repr = (const float*)d_in[0];
    const int*   edges     = (const int*)d_in[1];
    const float* ew        = (const float*)d_in[2];
    const float *p0g = (const float*)d_in[3],  *p0b = (const float*)d_in[4],
                *p0m = (const float*)d_in[5],  *p0v = (const float*)d_in[6],
                *p0W = (const float*)d_in[7],  *p0bi = (const float*)d_in[8];
    const float *p1g = (const float*)d_in[9],  *p1b = (const float*)d_in[10],
                *p1m = (const float*)d_in[11], *p1v = (const float*)d_in[12],
                *p1W = (const float*)d_in[13], *p1bi = (const float*)d_in[14];
    const float *u0g = (const float*)d_in[15], *u0b = (const float*)d_in[16],
                *u0m = (const float*)d_in[17], *u0v = (const float*)d_in[18],
                *u0W = (const float*)d_in[19], *u0bi = (const float*)d_in[20];
    const float *u1g = (const float*)d_in[21], *u1b = (const float*)d_in[22],
                *u1m = (const float*)d_in[23], *u1v = (const float*)d_in[24],
                *u1W = (const float*)d_in[25], *u1bi = (const float*)d_in[26];
    float* out = (float*)d_out;

    float *Wp0, *Wp1, *Wu0, *Wu1, *bp0, *bp1, *bu0, *bu1, *T, *P, *AGG, *PART;
    int *cntp, *curp;
    cudaGetSymbolAddress((void**)&Wp0, g_Wp0);
    cudaGetSymbolAddress((void**)&Wp1, g_Wp1);
    cudaGetSymbolAddress((void**)&Wu0, g_Wu0);
    cudaGetSymbolAddress((void**)&Wu1, g_Wu1);
    cudaGetSymbolAddress((void**)&bp0, g_bp0);
    cudaGetSymbolAddress((void**)&bp1, g_bp1);
    cudaGetSymbolAddress((void**)&bu0, g_bu0);
    cudaGetSymbolAddress((void**)&bu1, g_bu1);
    cudaGetSymbolAddress((void**)&T,    g_T);
    cudaGetSymbolAddress((void**)&P,    g_P);
    cudaGetSymbolAddress((void**)&AGG,  g_AGG);
    cudaGetSymbolAddress((void**)&PART, g_PART);
    cudaGetSymbolAddress((void**)&cntp, g_cnt);
    cudaGetSymbolAddress((void**)&curp, g_cur);

    cudaStream_t s0 = 0, s1 = sp.s1, s2 = sp.s2;
    const int gm = (NN + BM - 1) / BM;

    // fork point
    cudaEventRecord(sp.ev_root, s0);
    cudaStreamWaitEvent(s1, sp.ev_root, 0);

    // --- s1: CSR chain (independent of weights) ---
    cudaMemsetAsync(cntp, 0, NN * sizeof(int), s1);
    cudaMemsetAsync(curp, 0, NN * sizeof(int), s1);
    count_kernel<<<(EE + 255) / 256, 256, 0, s1>>>(edges);
    scanA_kernel<<<SCAN_NB, SCAN_B, 0, s1>>>();
    scanB_kernel<<<1, SCAN_B, 0, s1>>>();
    scanC_kernel<<<SCAN_NB, SCAN_B, 0, s1>>>();
    fill_kernel<<<(EE + 255) / 256, 256, 0, s1>>>(edges, ew);
    cudaEventRecord(sp.ev_csr, s1);

    // --- s0: fold ---
    FoldArgs fa0 = {p0g, p0b, p0m, p0v, p0W, p0bi, Wp0, bp0, DD};
    FoldArgs fa1 = {p1g, p1b, p1m, p1v, p1W, p1bi, Wp1, bp1, HH};
    FoldArgs fa2 = {u0g, u0b, u0m, u0v, u0W, u0bi, Wu0, bu0, KU};
    FoldArgs fa3 = {u1g, u1b, u1m, u1v, u1W, u1bi, Wu1, bu1, HH};
    fold4_kernel<<<dim3(128, 4), 256, 0, s0>>>(fa0, fa1, fa2, fa3);
    cudaEventRecord(sp.ev_fold, s0);

    // --- s2: upd0 partial = node_repr @ Wu0[0:128] (needs only fold) ---
    cudaStreamWaitEvent(s2, sp.ev_fold, 0);
    gemm_tf32_k128<1><<<gm, 256, 0, s2>>>(node_repr, Wu0, nullptr, nullptr, PART, NN);
    cudaEventRecord(sp.ev_u0a, s2);

    // --- s0: prep FFN ---
    gemm_tf32_k128<0><<<gm, 256, 0, s0>>>(node_repr, Wp0, bp0, nullptr, T, NN);
    gemm_tf32_k128<0><<<gm, 256, 0, s0>>>(T,         Wp1, bp1, nullptr, P, NN);

    // join CSR, aggregate
    cudaStreamWaitEvent(s0, sp.ev_csr, 0);
    aggregate_kernel<<<(NN * 32 + 255) / 256, 256, 0, s0>>>();

    // join upd0 partial; upd0b: gelu(AGG @ Wu0[128:256] + PART + bias)
    cudaStreamWaitEvent(s0, sp.ev_u0a, 0);
    gemm_tf32_k128<2><<<gm, 256, 0, s0>>>(AGG, Wu0 + 128 * 128, bu0, PART, T, NN);
    gemm_tf32_k128<0><<<gm, 256, 0, s0>>>(T, Wu1, bu1, nullptr, out, NN);
}

// round 10
// speedup vs baseline: 2.3931x; 1.0378x over previous
#include <cuda_runtime.h>
#include <cuda_fp16.h>
#include <math.h>
#include <stdint.h>

#define NN 50000
#define EE 800000
#define DD 128
#define HH 128
#define KU (DD + HH)
#define BN_EPS 1e-3f

#define SCAN_B 256
#define SCAN_NB ((NN + SCAN_B - 1) / SCAN_B)   // 196

// ---------------- scratch (device globals; no allocation allowed) ----------
__device__ float  g_T[NN * HH];      // FFN intermediate
__device__ __half g_Ph[NN * HH];     // prep output per node (fp16)
__device__ float  g_AGG[NN * HH];    // aggregated neighbour messages
__device__ float  g_PART[NN * HH];   // upd0 partial (node_repr @ Wu0_top)
__device__ float  g_Wp0[DD * HH];
__device__ float  g_Wp1[HH * HH];
__device__ float  g_Wu0[KU * HH];
__device__ float  g_Wu1[HH * HH];
__device__ float  g_bp0[HH], g_bp1[HH], g_bu0[HH], g_bu1[HH];
// CSR combined: [cnt NN][cur NN][base 1][start NN]  (first 2NN+1 zeroed per call)
__device__ int    g_csr[3 * NN + 1];
__device__ int    g_nbr[EE];
__device__ float  g_wgt[EE];

#define CSR_CNT   (g_csr)
#define CSR_CUR   (g_csr + NN)
#define CSR_BASE  (g_csr + 2 * NN)
#define CSR_START (g_csr + 2 * NN + 1)

// ---------------- streams/events (lazy init on first, non-captured call) ----
struct StreamPack {
    cudaStream_t s1, s2;
    cudaEvent_t ev_root, ev_fold, ev_csr, ev_u0a;
    StreamPack() {
        cudaStreamCreateWithFlags(&s1, cudaStreamNonBlocking);
        cudaStreamCreateWithFlags(&s2, cudaStreamNonBlocking);
        cudaEventCreateWithFlags(&ev_root, cudaEventDisableTiming);
        cudaEventCreateWithFlags(&ev_fold, cudaEventDisableTiming);
        cudaEventCreateWithFlags(&ev_csr,  cudaEventDisableTiming);
        cudaEventCreateWithFlags(&ev_u0a,  cudaEventDisableTiming);
    }
};

// tf32 conversion: destination MUST be a .b32 register in PTX
__device__ __forceinline__ uint32_t to_tf32_bits(float x) {
    uint32_t r;
    asm("cvt.rna.tf32.f32 %0, %1;" : "=r"(r) : "f"(x));
    return r;
}

// ---------------- BN fold (4 matrices, one launch) --------------------------
struct FoldArgs {
    const float *g, *b, *m, *v, *W, *bi;
    float *Wo, *bo;
    int K;
};

__global__ void fold4_kernel(FoldArgs a0, FoldArgs a1, FoldArgs a2, FoldArgs a3) {
    FoldArgs a;
    switch (blockIdx.y) {
        case 0: a = a0; break;
        case 1: a = a1; break;
        case 2: a = a2; break;
        default: a = a3; break;
    }
    int j = blockIdx.x;
    int k = threadIdx.x;
    __shared__ float red[256];
    float contrib = 0.0f;
    if (k < a.K) {
        float s = a.g[k] * rsqrtf(a.v[k] + BN_EPS);
        float t = a.b[k] - a.m[k] * s;
        float w = a.W[k * HH + j];
        a.Wo[k * HH + j] = __uint_as_float(to_tf32_bits(s * w));
        contrib = t * w;
    }
    red[k] = contrib;
    __syncthreads();
    for (int st = 128; st > 0; st >>= 1) {
        if (k < st) red[k] += red[k + st];
        __syncthreads();
    }
    if (k == 0) a.bo[j] = a.bi[j] + red[0];
}

// ---------------- CSR build --------------------------------------------------
__global__ void count_kernel(const int* __restrict__ edges) {
    int e = blockIdx.x * blockDim.x + threadIdx.x;
    if (e < EE) atomicAdd(&CSR_CNT[edges[e]], 1);
}

// fused scan: block-local inclusive scan + atomic block base (arrival order).
// start[] is NOT monotone in node id, but gives each node a unique range
// [start[i], start[i]+cnt[i]) — all aggregate needs.
__global__ void scan_fused_kernel() {
    __shared__ int sh[SCAN_B];
    __shared__ int base_sh;
    int t = threadIdx.x;
    int i = blockIdx.x * SCAN_B + t;
    int v = (i < NN) ? CSR_CNT[i] : 0;
    sh[t] = v;
    __syncthreads();
    for (int ofs = 1; ofs < SCAN_B; ofs <<= 1) {
        int u = (t >= ofs) ? sh[t - ofs] : 0;
        __syncthreads();
        sh[t] += u;
        __syncthreads();
    }
    if (t == SCAN_B - 1) base_sh = atomicAdd(CSR_BASE, sh[t]);
    __syncthreads();
    if (i < NN) CSR_START[i] = base_sh + sh[t] - v;   // exclusive local + block base
}

__global__ void fill_kernel(const int* __restrict__ edges, const float* __restrict__ ew) {
    int e = blockIdx.x * blockDim.x + threadIdx.x;
    if (e < EE) {
        int dst = edges[e];
        int nbr = edges[EE + e];
        int pos = CSR_START[dst] + atomicAdd(&CSR_CUR[dst], 1);
        g_nbr[pos] = nbr;
        g_wgt[pos] = ew[e];
    }
}

// ---------------- aggregation: one warp per node, gather fp16 rows ----------
__global__ void aggregate_kernel() {
    int node = (blockIdx.x * blockDim.x + threadIdx.x) >> 5;
    int lane = threadIdx.x & 31;
    if (node >= NN) return;
    int s = CSR_START[node];
    int cnt = CSR_CNT[node];
    int e = s + cnt;
    float4 acc = make_float4(0.f, 0.f, 0.f, 0.f);
    int i = s;
    for (; i + 4 <= e; i += 4) {
        int   nb0 = __ldg(&g_nbr[i]),     nb1 = __ldg(&g_nbr[i + 1]);
        int   nb2 = __ldg(&g_nbr[i + 2]), nb3 = __ldg(&g_nbr[i + 3]);
        float w0 = __ldg(&g_wgt[i]),      w1 = __ldg(&g_wgt[i + 1]);
        float w2 = __ldg(&g_wgt[i + 2]),  w3 = __ldg(&g_wgt[i + 3]);
        const __half2* p0 = (const __half2*)&g_Ph[nb0 * HH + lane * 4];
        const __half2* p1 = (const __half2*)&g_Ph[nb1 * HH + lane * 4];
        const __half2* p2 = (const __half2*)&g_Ph[nb2 * HH + lane * 4];
        const __half2* p3 = (const __half2*)&g_Ph[nb3 * HH + lane * 4];
        float2 a0 = __half22float2(p0[0]), b0 = __half22float2(p0[1]);
        float2 a1 = __half22float2(p1[0]), b1 = __half22float2(p1[1]);
        float2 a2 = __half22float2(p2[0]), b2 = __half22float2(p2[1]);
        float2 a3 = __half22float2(p3[0]), b3 = __half22float2(p3[1]);
        acc.x += w0 * a0.x + w1 * a1.x + w2 * a2.x + w3 * a3.x;
        acc.y += w0 * a0.y + w1 * a1.y + w2 * a2.y + w3 * a3.y;
        acc.z += w0 * b0.x + w1 * b1.x + w2 * b2.x + w3 * b3.x;
        acc.w += w0 * b0.y + w1 * b1.y + w2 * b2.y + w3 * b3.y;
    }
    for (; i < e; i++) {
        int nb  = __ldg(&g_nbr[i]);
        float w = __ldg(&g_wgt[i]);
        const __half2* p = (const __half2*)&g_Ph[nb * HH + lane * 4];
        float2 a = __half22float2(p[0]), b = __half22float2(p[1]);
        acc.x += w * a.x; acc.y += w * a.y; acc.z += w * b.x; acc.w += w * b.y;
    }
    float inv = (cnt > 0) ? 1.0f / (float)cnt : 0.0f;
    acc.x *= inv; acc.y *= inv; acc.z *= inv; acc.w *= inv;
    *(float4*)&g_AGG[node * HH + lane * 4] = acc;
}

// ---------------- tf32 tensor-core GEMM, K=128 fixed ------------------------
// MODE 0: C = gelu(acc + bias)               (fp32 out)
// MODE 1: C = acc                            (raw partial, fp32 out)
// MODE 2: C = gelu(acc + bias + Cadd)        (fp32 out)
// MODE 3: C = gelu(acc + bias)               (fp16 out, packed half2)
__device__ __forceinline__ float gelu_exact(float x) {
    return 0.5f * x * (1.0f + erff(x * 0.70710678118654752f));
}

__device__ __forceinline__ void mma_tf32(float* d, const uint32_t* a, const uint32_t* b) {
    asm volatile(
        "mma.sync.aligned.m16n8k8.row.col.f32.tf32.tf32.f32 "
        "{%0,%1,%2,%3}, {%4,%5,%6,%7}, {%8,%9}, {%0,%1,%2,%3};\n"
        : "+f"(d[0]), "+f"(d[1]), "+f"(d[2]), "+f"(d[3])
        : "r"(a[0]), "r"(a[1]), "r"(a[2]), "r"(a[3]), "r"(b[0]), "r"(b[1]));
}

#define BM 128
#define BK 16
#define KK 128
#define AS_STRIDE 20
#define BS_STRIDE 136

template <int MODE>
__global__ __launch_bounds__(256, 2) void gemm_tf32_k128(
    const float* __restrict__ A,
    const float* __restrict__ W, const float* __restrict__ bias,
    const float* __restrict__ Cadd,
    void* __restrict__ Cv, int M)
{
    __shared__ float As[BM][AS_STRIDE];
    __shared__ float Bs[BK][BS_STRIDE];

    const int tid  = threadIdx.x;
    const int lane = tid & 31;
    const int wid  = tid >> 5;
    const int wm = (wid & 3) * 32;
    const int wn = (wid >> 2) * 64;
    const int bm = blockIdx.x * BM;

    const int alr = tid >> 1;
    const int alc = (tid & 1) * 8;
    const int grow = bm + alr;
    const bool rok = (grow < M);
    const int blk = tid >> 4;
    const int blc = (tid & 15) * 8;

    const int gi = lane >> 2;
    const int ti = lane & 3;

    float acc[2][8][4];
#pragma unroll
    for (int i = 0; i < 2; i++)
#pragma unroll
        for (int j = 0; j < 8; j++)
#pragma unroll
            for (int c = 0; c < 4; c++) acc[i][j][c] = 0.0f;

    float4 av0 = make_float4(0.f,0.f,0.f,0.f), av1 = av0, bv0, bv1;
    if (rok) {
        const float* ap = &A[grow * KK + alc];
        av0 = *(const float4*)(ap);
        av1 = *(const float4*)(ap + 4);
    }
    bv0 = *(const float4*)&W[blk * 128 + blc];
    bv1 = *(const float4*)&W[blk * 128 + blc + 4];

#pragma unroll
    for (int kc = 0; kc < KK; kc += BK) {
        __syncthreads();
        As[alr][alc + 0] = __uint_as_float(to_tf32_bits(av0.x));
        As[alr][alc + 1] = __uint_as_float(to_tf32_bits(av0.y));
        As[alr][alc + 2] = __uint_as_float(to_tf32_bits(av0.z));
        As[alr][alc + 3] = __uint_as_float(to_tf32_bits(av0.w));
        As[alr][alc + 4] = __uint_as_float(to_tf32_bits(av1.x));
        As[alr][alc + 5] = __uint_as_float(to_tf32_bits(av1.y));
        As[alr][alc + 6] = __uint_as_float(to_tf32_bits(av1.z));
        As[alr][alc + 7] = __uint_as_float(to_tf32_bits(av1.w));
        *(float4*)&Bs[blk][blc]     = bv0;
        *(float4*)&Bs[blk][blc + 4] = bv1;
        __syncthreads();

        if (kc + BK < KK) {
            if (rok) {
                const float* ap = &A[grow * KK + kc + BK + alc];
                av0 = *(const float4*)(ap);
                av1 = *(const float4*)(ap + 4);
            }
            bv0 = *(const float4*)&W[(kc + BK + blk) * 128 + blc];
            bv1 = *(const float4*)&W[(kc + BK + blk) * 128 + blc + 4];
        }

#pragma unroll
        for (int ks = 0; ks < 2; ks++) {
            const int k0 = ks * 8;
            uint32_t af[2][4];
#pragma unroll
            for (int i = 0; i < 2; i++) {
                const int r = wm + 16 * i + gi;
                af[i][0] = __float_as_uint(As[r][k0 + ti]);
                af[i][1] = __float_as_uint(As[r + 8][k0 + ti]);
                af[i][2] = __float_as_uint(As[r][k0 + ti + 4]);
                af[i][3] = __float_as_uint(As[r + 8][k0 + ti + 4]);
            }
            uint32_t bf[8][2];
#pragma unroll
            for (int j = 0; j < 8; j++) {
                const int col = wn + 8 * j + gi;
                bf[j][0] = __float_as_uint(Bs[k0 + ti][col]);
                bf[j][1] = __float_as_uint(Bs[k0 + ti + 4][col]);
            }
#pragma unroll
            for (int i = 0; i < 2; i++)
#pragma unroll
                for (int j = 0; j < 8; j++)
                    mma_tf32(acc[i][j], af[i], bf[j]);
        }
    }

    float* C = (float*)Cv;
    __half* Ch = (__half*)Cv;
#pragma unroll
    for (int j = 0; j < 8; j++) {
        const int col = wn + 8 * j + ti * 2;
        float b0 = 0.f, b1 = 0.f;
        if (MODE != 1) { b0 = bias[col]; b1 = bias[col + 1]; }
#pragma unroll
        for (int i = 0; i < 2; i++) {
            const int r0 = bm + wm + 16 * i + gi;
            const int r1 = r0 + 8;
            if (r0 < M) {
                if (MODE == 1) {
                    *(float2*)&C[r0 * 128 + col] = make_float2(acc[i][j][0], acc[i][j][1]);
                } else if (MODE == 2) {
                    float2 o;
                    o.x = gelu_exact(acc[i][j][0] + b0 + Cadd[r0 * 128 + col]);
                    o.y = gelu_exact(acc[i][j][1] + b1 + Cadd[r0 * 128 + col + 1]);
                    *(float2*)&C[r0 * 128 + col] = o;
                } else if (MODE == 3) {
                    float gx = gelu_exact(acc[i][j][0] + b0);
                    float gy = gelu_exact(acc[i][j][1] + b1);
                    *(__half2*)&Ch[r0 * 128 + col] = __floats2half2_rn(gx, gy);
                } else {
                    float2 o;
                    o.x = gelu_exact(acc[i][j][0] + b0);
                    o.y = gelu_exact(acc[i][j][1] + b1);
                    *(float2*)&C[r0 * 128 + col] = o;
                }
            }
            if (r1 < M) {
                if (MODE == 1) {
                    *(float2*)&C[r1 * 128 + col] = make_float2(acc[i][j][2], acc[i][j][3]);
                } else if (MODE == 2) {
                    float2 o;
                    o.x = gelu_exact(acc[i][j][2] + b0 + Cadd[r1 * 128 + col]);
                    o.y = gelu_exact(acc[i][j][3] + b1 + Cadd[r1 * 128 + col + 1]);
                    *(float2*)&C[r1 * 128 + col] = o;
                } else if (MODE == 3) {
                    float gx = gelu_exact(acc[i][j][2] + b0);
                    float gy = gelu_exact(acc[i][j][3] + b1);
                    *(__half2*)&Ch[r1 * 128 + col] = __floats2half2_rn(gx, gy);
                } else {
                    float2 o;
                    o.x = gelu_exact(acc[i][j][2] + b0);
                    o.y = gelu_exact(acc[i][j][3] + b1);
                    *(float2*)&C[r1 * 128 + col] = o;
                }
            }
        }
    }
}

// ---------------- launch -----------------------------------------------------
extern "C" void kernel_launch(void* const* d_in, const int* in_sizes, int n_in,
                              void* d_out, int out_size) {
    static StreamPack sp;   // first call = correctness run (not captured)

    const float* node_repr = (const float*)d_in[0];
    const int*   edges     = (const int*)d_in[1];
    const float* ew        = (const float*)d_in[2];
    const float *p0g = (const float*)d_in[3],  *p0b = (const float*)d_in[4],
                *p0m = (const float*)d_in[5],  *p0v = (const float*)d_in[6],
                *p0W = (const float*)d_in[7],  *p0bi = (const float*)d_in[8];
    const float *p1g = (const float*)d_in[9],  *p1b = (const float*)d_in[10],
                *p1m = (const float*)d_in[11], *p1v = (const float*)d_in[12],
                *p1W = (const float*)d_in[13], *p1bi = (const float*)d_in[14];
    const float *u0g = (const float*)d_in[15], *u0b = (const float*)d_in[16],
                *u0m = (const float*)d_in[17], *u0v = (const float*)d_in[18],
                *u0W = (const float*)d_in[19], *u0bi = (const float*)d_in[20];
    const float *u1g = (const float*)d_in[21], *u1b = (const float*)d_in[22],
                *u1m = (const float*)d_in[23], *u1v = (const float*)d_in[24],
                *u1W = (const float*)d_in[25], *u1bi = (const float*)d_in[26];
    float* out = (float*)d_out;

    float *Wp0, *Wp1, *Wu0, *Wu1, *bp0, *bp1, *bu0, *bu1, *T, *AGG, *PART;
    __half* Ph;
    int* csr;
    cudaGetSymbolAddress((void**)&Wp0, g_Wp0);
    cudaGetSymbolAddress((void**)&Wp1, g_Wp1);
    cudaGetSymbolAddress((void**)&Wu0, g_Wu0);
    cudaGetSymbolAddress((void**)&Wu1, g_Wu1);
    cudaGetSymbolAddress((void**)&bp0, g_bp0);
    cudaGetSymbolAddress((void**)&bp1, g_bp1);
    cudaGetSymbolAddress((void**)&bu0, g_bu0);
    cudaGetSymbolAddress((void**)&bu1, g_bu1);
    cudaGetSymbolAddress((void**)&T,    g_T);
    cudaGetSymbolAddress((void**)&Ph,   g_Ph);
    cudaGetSymbolAddress((void**)&AGG,  g_AGG);
    cudaGetSymbolAddress((void**)&PART, g_PART);
    cudaGetSymbolAddress((void**)&csr,  g_csr);

    cudaStream_t s0 = 0, s1 = sp.s1, s2 = sp.s2;
    const int gm = (NN + BM - 1) / BM;

    // fork point
    cudaEventRecord(sp.ev_root, s0);
    cudaStreamWaitEvent(s1, sp.ev_root, 0);

    // --- s1: CSR chain (4 nodes) ---
    cudaMemsetAsync(csr, 0, (2 * NN + 1) * sizeof(int), s1);   // cnt+cur+base
    count_kernel<<<(EE + 255) / 256, 256, 0, s1>>>(edges);
    scan_fused_kernel<<<SCAN_NB, SCAN_B, 0, s1>>>();
    fill_kernel<<<(EE + 255) / 256, 256, 0, s1>>>(edges, ew);
    cudaEventRecord(sp.ev_csr, s1);

    // --- s0: fold ---
    FoldArgs fa0 = {p0g, p0b, p0m, p0v, p0W, p0bi, Wp0, bp0, DD};
    FoldArgs fa1 = {p1g, p1b, p1m, p1v, p1W, p1bi, Wp1, bp1, HH};
    FoldArgs fa2 = {u0g, u0b, u0m, u0v, u0W, u0bi, Wu0, bu0, KU};
    FoldArgs fa3 = {u1g, u1b, u1m, u1v, u1W, u1bi, Wu1, bu1, HH};
    fold4_kernel<<<dim3(128, 4), 256, 0, s0>>>(fa0, fa1, fa2, fa3);
    cudaEventRecord(sp.ev_fold, s0);

    // --- s2: upd0 partial = node_repr @ Wu0[0:128] ---
    cudaStreamWaitEvent(s2, sp.ev_fold, 0);
    gemm_tf32_k128<1><<<gm, 256, 0, s2>>>(node_repr, Wu0, nullptr, nullptr, PART, NN);
    cudaEventRecord(sp.ev_u0a, s2);

    // --- s0: prep FFN (prep1 emits fp16 P) ---
    gemm_tf32_k128<0><<<gm, 256, 0, s0>>>(node_repr, Wp0, bp0, nullptr, T, NN);
    gemm_tf32_k128<3><<<gm, 256, 0, s0>>>(T,         Wp1, bp1, nullptr, Ph, NN);

    // join CSR, aggregate (fp16 gathers)
    cudaStreamWaitEvent(s0, sp.ev_csr, 0);
    aggregate_kernel<<<(NN * 32 + 255) / 256, 256, 0, s0>>>();

    // join upd0 partial; upd0b: gelu(AGG @ Wu0[128:256] + PART + bias)
    cudaStreamWaitEvent(s0, sp.ev_u0a, 0);
    gemm_tf32_k128<2><<<gm, 256, 0, s0>>>(AGG, Wu0 + 128 * 128, bu0, PART, T, NN);
    gemm_tf32_k128<0><<<gm, 256, 0, s0>>>(T, Wu1, bu1, nullptr, out, NN);
}

// round 11
// speedup vs baseline: 2.7292x; 1.1404x over previous
#include <cuda_runtime.h>
#include <cuda_fp16.h>
#include <math.h>
#include <stdint.h>

#define NN 50000
#define EE 800000
#define DD 128
#define HH 128
#define KU (DD + HH)
#define BN_EPS 1e-3f

#define SCAN_B 256
#define SCAN_NB ((NN + SCAN_B - 1) / SCAN_B)   // 196

// ---------------- scratch (device globals; no allocation allowed) ----------
__device__ float  g_T[NN * HH];      // FFN intermediate
__device__ __half g_Ph[NN * HH];     // prep output per node (fp16)
__device__ float  g_AGG[NN * HH];    // aggregated neighbour messages
__device__ float  g_PART[NN * HH];   // upd0 partial (node_repr @ Wu0_top)
// weights: fp16, n-major  Wh[n][k]
__device__ __half g_Wp0h[HH * DD];
__device__ __half g_Wp1h[HH * HH];
__device__ __half g_Wu0h[HH * KU];   // row stride KU=256
__device__ __half g_Wu1h[HH * HH];
__device__ float  g_bp0[HH], g_bp1[HH], g_bu0[HH], g_bu1[HH];
// CSR combined: [cnt NN][cur NN][base 1][start NN]  (first 2NN+1 zeroed per call)
__device__ int    g_csr[3 * NN + 1];
__device__ int    g_nbr[EE];
__device__ float  g_wgt[EE];

#define CSR_CNT   (g_csr)
#define CSR_CUR   (g_csr + NN)
#define CSR_BASE  (g_csr + 2 * NN)
#define CSR_START (g_csr + 2 * NN + 1)

// ---------------- streams/events (lazy init on first, non-captured call) ----
struct StreamPack {
    cudaStream_t s1, s2;
    cudaEvent_t ev_root, ev_fold, ev_csr, ev_u0a;
    StreamPack() {
        cudaStreamCreateWithFlags(&s1, cudaStreamNonBlocking);
        cudaStreamCreateWithFlags(&s2, cudaStreamNonBlocking);
        cudaEventCreateWithFlags(&ev_root, cudaEventDisableTiming);
        cudaEventCreateWithFlags(&ev_fold, cudaEventDisableTiming);
        cudaEventCreateWithFlags(&ev_csr,  cudaEventDisableTiming);
        cudaEventCreateWithFlags(&ev_u0a,  cudaEventDisableTiming);
    }
};

// ---------------- BN fold (4 matrices, one launch) --------------------------
// Writes Wh[n][k] = fp16(s[k]*W[k][n]); bias fp32 from fp32 math.
struct FoldArgs {
    const float *g, *b, *m, *v, *W, *bi;
    __half *Wo;
    float *bo;
    int K, ldw;
};

__global__ void fold4_kernel(FoldArgs a0, FoldArgs a1, FoldArgs a2, FoldArgs a3) {
    FoldArgs a;
    switch (blockIdx.y) {
        case 0: a = a0; break;
        case 1: a = a1; break;
        case 2: a = a2; break;
        default: a = a3; break;
    }
    int j = blockIdx.x;        // output column (n) 0..127
    int k = threadIdx.x;       // input row (k), blockDim = 256
    __shared__ float red[256];
    float contrib = 0.0f;
    if (k < a.K) {
        float s = a.g[k] * rsqrtf(a.v[k] + BN_EPS);
        float t = a.b[k] - a.m[k] * s;
        float w = a.W[k * HH + j];
        a.Wo[j * a.ldw + k] = __float2half(s * w);   // transposed, fp16
        contrib = t * w;
    }
    red[k] = contrib;
    __syncthreads();
    for (int st = 128; st > 0; st >>= 1) {
        if (k < st) red[k] += red[k + st];
        __syncthreads();
    }
    if (k == 0) a.bo[j] = a.bi[j] + red[0];
}

// ---------------- CSR build --------------------------------------------------
__global__ void count_kernel(const int* __restrict__ edges) {
    int e = blockIdx.x * blockDim.x + threadIdx.x;
    if (e < EE) atomicAdd(&CSR_CNT[edges[e]], 1);
}

__global__ void scan_fused_kernel() {
    __shared__ int sh[SCAN_B];
    __shared__ int base_sh;
    int t = threadIdx.x;
    int i = blockIdx.x * SCAN_B + t;
    int v = (i < NN) ? CSR_CNT[i] : 0;
    sh[t] = v;
    __syncthreads();
    for (int ofs = 1; ofs < SCAN_B; ofs <<= 1) {
        int u = (t >= ofs) ? sh[t - ofs] : 0;
        __syncthreads();
        sh[t] += u;
        __syncthreads();
    }
    if (t == SCAN_B - 1) base_sh = atomicAdd(CSR_BASE, sh[t]);
    __syncthreads();
    if (i < NN) CSR_START[i] = base_sh + sh[t] - v;
}

__global__ void fill_kernel(const int* __restrict__ edges, const float* __restrict__ ew) {
    int e = blockIdx.x * blockDim.x + threadIdx.x;
    if (e < EE) {
        int dst = edges[e];
        int nbr = edges[EE + e];
        int pos = CSR_START[dst] + atomicAdd(&CSR_CUR[dst], 1);
        g_nbr[pos] = nbr;
        g_wgt[pos] = ew[e];
    }
}

// ---------------- aggregation: one warp per node, gather fp16 rows ----------
__global__ void aggregate_kernel() {
    int node = (blockIdx.x * blockDim.x + threadIdx.x) >> 5;
    int lane = threadIdx.x & 31;
    if (node >= NN) return;
    int s = CSR_START[node];
    int cnt = CSR_CNT[node];
    int e = s + cnt;
    float4 acc = make_float4(0.f, 0.f, 0.f, 0.f);
    int i = s;
    for (; i + 4 <= e; i += 4) {
        int   nb0 = __ldg(&g_nbr[i]),     nb1 = __ldg(&g_nbr[i + 1]);
        int   nb2 = __ldg(&g_nbr[i + 2]), nb3 = __ldg(&g_nbr[i + 3]);
        float w0 = __ldg(&g_wgt[i]),      w1 = __ldg(&g_wgt[i + 1]);
        float w2 = __ldg(&g_wgt[i + 2]),  w3 = __ldg(&g_wgt[i + 3]);
        const __half2* p0 = (const __half2*)&g_Ph[nb0 * HH + lane * 4];
        const __half2* p1 = (const __half2*)&g_Ph[nb1 * HH + lane * 4];
        const __half2* p2 = (const __half2*)&g_Ph[nb2 * HH + lane * 4];
        const __half2* p3 = (const __half2*)&g_Ph[nb3 * HH + lane * 4];
        float2 a0 = __half22float2(p0[0]), b0 = __half22float2(p0[1]);
        float2 a1 = __half22float2(p1[0]), b1 = __half22float2(p1[1]);
        float2 a2 = __half22float2(p2[0]), b2 = __half22float2(p2[1]);
        float2 a3 = __half22float2(p3[0]), b3 = __half22float2(p3[1]);
        acc.x += w0 * a0.x + w1 * a1.x + w2 * a2.x + w3 * a3.x;
        acc.y += w0 * a0.y + w1 * a1.y + w2 * a2.y + w3 * a3.y;
        acc.z += w0 * b0.x + w1 * b1.x + w2 * b2.x + w3 * b3.x;
        acc.w += w0 * b0.y + w1 * b1.y + w2 * b2.y + w3 * b3.y;
    }
    for (; i < e; i++) {
        int nb  = __ldg(&g_nbr[i]);
        float w = __ldg(&g_wgt[i]);
        const __half2* p = (const __half2*)&g_Ph[nb * HH + lane * 4];
        float2 a = __half22float2(p[0]), b = __half22float2(p[1]);
        acc.x += w * a.x; acc.y += w * a.y; acc.z += w * b.x; acc.w += w * b.y;
    }
    float inv = (cnt > 0) ? 1.0f / (float)cnt : 0.0f;
    acc.x *= inv; acc.y *= inv; acc.z *= inv; acc.w *= inv;
    *(float4*)&g_AGG[node * HH + lane * 4] = acc;
}

// ---------------- fp16 tensor-core GEMM, K=128 fixed ------------------------
// C[M x 128] = f(A[M x 128] @ Wh^T + ...), Wh is fp16 [n][k] with row stride ldb.
// MODE 0: C = gelu(acc + bias)               (fp32 out)
// MODE 1: C = acc                            (raw partial, fp32 out)
// MODE 2: C = gelu(acc + bias + Cadd)        (fp32 out)
// MODE 3: C = gelu(acc + bias)               (fp16 out, packed half2)
__device__ __forceinline__ float gelu_exact(float x) {
    return 0.5f * x * (1.0f + erff(x * 0.70710678118654752f));
}

__device__ __forceinline__ void mma_f16(float* d, const uint32_t* a, const uint32_t* b) {
    asm volatile(
        "mma.sync.aligned.m16n8k16.row.col.f32.f16.f16.f32 "
        "{%0,%1,%2,%3}, {%4,%5,%6,%7}, {%8,%9}, {%0,%1,%2,%3};\n"
        : "+f"(d[0]), "+f"(d[1]), "+f"(d[2]), "+f"(d[3])
        : "r"(a[0]), "r"(a[1]), "r"(a[2]), "r"(a[3]), "r"(b[0]), "r"(b[1]));
}

#define BM 128
#define BK 16
#define KK 128
#define HS 24      // smem row stride in halves (16 + 8 pad): conflict-free frags

template <int MODE>
__global__ __launch_bounds__(256, 2) void gemm_f16_k128(
    const float* __restrict__ A,
    const __half* __restrict__ Wh, int ldb,
    const float* __restrict__ bias,
    const float* __restrict__ Cadd,
    void* __restrict__ Cv, int M)
{
    __shared__ __half As[BM][HS];   // [m][k]
    __shared__ __half Bs[BM][HS];   // [n][k]

    const int tid  = threadIdx.x;
    const int lane = tid & 31;
    const int wid  = tid >> 5;
    const int wm = (wid & 3) * 32;
    const int wn = (wid >> 2) * 64;
    const int bm = blockIdx.x * BM;

    // loaders: row = tid>>1 (128 rows), k-segment = (tid&1)*8 (8 halves each)
    const int lr  = tid >> 1;
    const int seg = (tid & 1) * 8;
    const int grow = bm + lr;
    const bool rok = (grow < M);

    const int gi = lane >> 2;
    const int ti = lane & 3;

    float acc[2][8][4];
#pragma unroll
    for (int i = 0; i < 2; i++)
#pragma unroll
        for (int j = 0; j < 8; j++)
#pragma unroll
            for (int c = 0; c < 4; c++) acc[i][j][c] = 0.0f;

    // prefetch registers
    float4 af0 = make_float4(0.f,0.f,0.f,0.f), af1 = af0;
    uint4  bfv;
    if (rok) {
        const float* ap = &A[grow * KK + seg];
        af0 = *(const float4*)(ap);
        af1 = *(const float4*)(ap + 4);
    }
    bfv = *(const uint4*)&Wh[lr * ldb + seg];

#pragma unroll
    for (int kc = 0; kc < KK; kc += BK) {
        __syncthreads();
        {
            __half2 h0 = __floats2half2_rn(af0.x, af0.y);
            __half2 h1 = __floats2half2_rn(af0.z, af0.w);
            __half2 h2 = __floats2half2_rn(af1.x, af1.y);
            __half2 h3 = __floats2half2_rn(af1.z, af1.w);
            uint4 av;
            av.x = *(uint32_t*)&h0; av.y = *(uint32_t*)&h1;
            av.z = *(uint32_t*)&h2; av.w = *(uint32_t*)&h3;
            *(uint4*)&As[lr][seg] = av;
            *(uint4*)&Bs[lr][seg] = bfv;
        }
        __syncthreads();

        if (kc + BK < KK) {
            if (rok) {
                const float* ap = &A[grow * KK + kc + BK + seg];
                af0 = *(const float4*)(ap);
                af1 = *(const float4*)(ap + 4);
            }
            bfv = *(const uint4*)&Wh[lr * ldb + kc + BK + seg];
        }

        // fragments + 16 MMAs for this 16-k block
        uint32_t af[2][4];
#pragma unroll
        for (int i = 0; i < 2; i++) {
            const int r = wm + 16 * i + gi;
            af[i][0] = *(const uint32_t*)&As[r][2 * ti];
            af[i][1] = *(const uint32_t*)&As[r + 8][2 * ti];
            af[i][2] = *(const uint32_t*)&As[r][2 * ti + 8];
            af[i][3] = *(const uint32_t*)&As[r + 8][2 * ti + 8];
        }
        uint32_t bf[8][2];
#pragma unroll
        for (int j = 0; j < 8; j++) {
            const int n = wn + 8 * j + gi;
            bf[j][0] = *(const uint32_t*)&Bs[n][2 * ti];
            bf[j][1] = *(const uint32_t*)&Bs[n][2 * ti + 8];
        }
#pragma unroll
        for (int i = 0; i < 2; i++)
#pragma unroll
            for (int j = 0; j < 8; j++)
                mma_f16(acc[i][j], af[i], bf[j]);
    }

    float* C = (float*)Cv;
    __half* Ch = (__half*)Cv;
#pragma unroll
    for (int j = 0; j < 8; j++) {
        const int col = wn + 8 * j + ti * 2;
        float b0 = 0.f, b1 = 0.f;
        if (MODE != 1) { b0 = bias[col]; b1 = bias[col + 1]; }
#pragma unroll
        for (int i = 0; i < 2; i++) {
            const int r0 = bm + wm + 16 * i + gi;
            const int r1 = r0 + 8;
            if (r0 < M) {
                if (MODE == 1) {
                    *(float2*)&C[r0 * 128 + col] = make_float2(acc[i][j][0], acc[i][j][1]);
                } else if (MODE == 2) {
                    float2 o;
                    o.x = gelu_exact(acc[i][j][0] + b0 + Cadd[r0 * 128 + col]);
                    o.y = gelu_exact(acc[i][j][1] + b1 + Cadd[r0 * 128 + col + 1]);
                    *(float2*)&C[r0 * 128 + col] = o;
                } else if (MODE == 3) {
                    float gx = gelu_exact(acc[i][j][0] + b0);
                    float gy = gelu_exact(acc[i][j][1] + b1);
                    *(__half2*)&Ch[r0 * 128 + col] = __floats2half2_rn(gx, gy);
                } else {
                    float2 o;
                    o.x = gelu_exact(acc[i][j][0] + b0);
                    o.y = gelu_exact(acc[i][j][1] + b1);
                    *(float2*)&C[r0 * 128 + col] = o;
                }
            }
            if (r1 < M) {
                if (MODE == 1) {
                    *(float2*)&C[r1 * 128 + col] = make_float2(acc[i][j][2], acc[i][j][3]);
                } else if (MODE == 2) {
                    float2 o;
                    o.x = gelu_exact(acc[i][j][2] + b0 + Cadd[r1 * 128 + col]);
                    o.y = gelu_exact(acc[i][j][3] + b1 + Cadd[r1 * 128 + col + 1]);
                    *(float2*)&C[r1 * 128 + col] = o;
                } else if (MODE == 3) {
                    float gx = gelu_exact(acc[i][j][2] + b0);
                    float gy = gelu_exact(acc[i][j][3] + b1);
                    *(__half2*)&Ch[r1 * 128 + col] = __floats2half2_rn(gx, gy);
                } else {
                    float2 o;
                    o.x = gelu_exact(acc[i][j][2] + b0);
                    o.y = gelu_exact(acc[i][j][3] + b1);
                    *(float2*)&C[r1 * 128 + col] = o;
                }
            }
        }
    }
}

// ---------------- launch -----------------------------------------------------
extern "C" void kernel_launch(void* const* d_in, const int* in_sizes, int n_in,
                              void* d_out, int out_size) {
    static StreamPack sp;   // first call = correctness run (not captured)

    const float* node_repr = (const float*)d_in[0];
    const int*   edges     = (const int*)d_in[1];
    const float* ew        = (const float*)d_in[2];
    const float *p0g = (const float*)d_in[3],  *p0b = (const float*)d_in[4],
                *p0m = (const float*)d_in[5],  *p0v = (const float*)d_in[6],
                *p0W = (const float*)d_in[7],  *p0bi = (const float*)d_in[8];
    const float *p1g = (const float*)d_in[9],  *p1b = (const float*)d_in[10],
                *p1m = (const float*)d_in[11], *p1v = (const float*)d_in[12],
                *p1W = (const float*)d_in[13], *p1bi = (const float*)d_in[14];
    const float *u0g = (const float*)d_in[15], *u0b = (const float*)d_in[16],
                *u0m = (const float*)d_in[17], *u0v = (const float*)d_in[18],
                *u0W = (const float*)d_in[19], *u0bi = (const float*)d_in[20];
    const float *u1g = (const float*)d_in[21], *u1b = (const float*)d_in[22],
                *u1m = (const float*)d_in[23], *u1v = (const float*)d_in[24],
                *u1W = (const float*)d_in[25], *u1bi = (const float*)d_in[26];
    float* out = (float*)d_out;

    __half *Wp0h, *Wp1h, *Wu0h, *Wu1h, *Ph;
    float *bp0, *bp1, *bu0, *bu1, *T, *AGG, *PART;
    int* csr;
    cudaGetSymbolAddress((void**)&Wp0h, g_Wp0h);
    cudaGetSymbolAddress((void**)&Wp1h, g_Wp1h);
    cudaGetSymbolAddress((void**)&Wu0h, g_Wu0h);
    cudaGetSymbolAddress((void**)&Wu1h, g_Wu1h);
    cudaGetSymbolAddress((void**)&bp0, g_bp0);
    cudaGetSymbolAddress((void**)&bp1, g_bp1);
    cudaGetSymbolAddress((void**)&bu0, g_bu0);
    cudaGetSymbolAddress((void**)&bu1, g_bu1);
    cudaGetSymbolAddress((void**)&T,    g_T);
    cudaGetSymbolAddress((void**)&Ph,   g_Ph);
    cudaGetSymbolAddress((void**)&AGG,  g_AGG);
    cudaGetSymbolAddress((void**)&PART, g_PART);
    cudaGetSymbolAddress((void**)&csr,  g_csr);

    cudaStream_t s0 = 0, s1 = sp.s1, s2 = sp.s2;
    const int gm = (NN + BM - 1) / BM;

    // fork point
    cudaEventRecord(sp.ev_root, s0);
    cudaStreamWaitEvent(s1, sp.ev_root, 0);

    // --- s1: CSR chain ---
    cudaMemsetAsync(csr, 0, (2 * NN + 1) * sizeof(int), s1);
    count_kernel<<<(EE + 255) / 256, 256, 0, s1>>>(edges);
    scan_fused_kernel<<<SCAN_NB, SCAN_B, 0, s1>>>();
    fill_kernel<<<(EE + 255) / 256, 256, 0, s1>>>(edges, ew);
    cudaEventRecord(sp.ev_csr, s1);

    // --- s0: fold (fp16 transposed weights) ---
    FoldArgs fa0 = {p0g, p0b, p0m, p0v, p0W, p0bi, Wp0h, bp0, DD, DD};
    FoldArgs fa1 = {p1g, p1b, p1m, p1v, p1W, p1bi, Wp1h, bp1, HH, HH};
    FoldArgs fa2 = {u0g, u0b, u0m, u0v, u0W, u0bi, Wu0h, bu0, KU, KU};
    FoldArgs fa3 = {u1g, u1b, u1m, u1v, u1W, u1bi, Wu1h, bu1, HH, HH};
    fold4_kernel<<<dim3(128, 4), 256, 0, s0>>>(fa0, fa1, fa2, fa3);
    cudaEventRecord(sp.ev_fold, s0);

    // --- s2: upd0 partial = node_repr @ Wu0[:, 0:128]  (Wu0h rows, k 0..127) ---
    cudaStreamWaitEvent(s2, sp.ev_fold, 0);
    gemm_f16_k128<1><<<gm, 256, 0, s2>>>(node_repr, Wu0h, KU, nullptr, nullptr, PART, NN);
    cudaEventRecord(sp.ev_u0a, s2);

    // --- s0: prep FFN (prep1 emits fp16 P) ---
    gemm_f16_k128<0><<<gm, 256, 0, s0>>>(node_repr, Wp0h, DD, bp0, nullptr, T, NN);
    gemm_f16_k128<3><<<gm, 256, 0, s0>>>(T,         Wp1h, HH, bp1, nullptr, Ph, NN);

    // join CSR, aggregate (fp16 gathers)
    cudaStreamWaitEvent(s0, sp.ev_csr, 0);
    aggregate_kernel<<<(NN * 32 + 255) / 256, 256, 0, s0>>>();

    // join upd0 partial; upd0b: gelu(AGG @ Wu0[:, 128:256] + PART + bias)
    cudaStreamWaitEvent(s0, sp.ev_u0a, 0);
    gemm_f16_k128<2><<<gm, 256, 0, s0>>>(AGG, Wu0h + 128, KU, bu0, PART, T, NN);
    gemm_f16_k128<0><<<gm, 256, 0, s0>>>(T, Wu1h, HH, bu1, nullptr, out, NN);
}